// round 1
// baseline (speedup 1.0000x reference)
#include <cuda_runtime.h>
#include <math.h>

// Problem constants
#define T_STEPS 256
#define BATCH   64
#define IDIM    1024
#define HDIM    1024
#define GDIM    4096              // 4 * HDIM (gate-major columns: g*1024 + h)
#define TBROWS  (T_STEPS * BATCH) // 16384

// ---------------------------------------------------------------------------
// Device scratch (static: no allocations allowed)
// ---------------------------------------------------------------------------
__device__ __align__(16) float g_Wx[(size_t)GDIM * IDIM];   // masked W_x, [4096][1024]
__device__ __align__(16) float g_Wh[(size_t)GDIM * HDIM];   // masked W_h, [4096][1024]
__device__ __align__(16) float g_XW[(size_t)TBROWS * GDIM]; // precomputed X @ Wx^T
__device__ __align__(16) float g_C [(size_t)BATCH * HDIM];  // cell state

// ---------------------------------------------------------------------------
// Packed fp32x2 FMA (Blackwell): 2 fp32 FMAs per instruction, full precision.
// ---------------------------------------------------------------------------
__device__ __forceinline__ void ffma2(unsigned long long &acc,
                                      unsigned long long a,
                                      unsigned long long b) {
    asm("fma.rn.f32x2 %0, %1, %2, %0;" : "+l"(acc) : "l"(a), "l"(b));
}

__device__ __forceinline__ float2 unpack2(unsigned long long v) {
    float2 r;
    asm("mov.b64 {%0, %1}, %2;" : "=f"(r.x), "=f"(r.y) : "l"(v));
    return r;
}

// ---------------------------------------------------------------------------
// Prep: apply masks to weights, init C.  1,048,576 threads, float4 each.
// ---------------------------------------------------------------------------
__global__ void prep_kernel(const float4* __restrict__ Wx, const float4* __restrict__ mx,
                            const float4* __restrict__ Wh, const float4* __restrict__ mh,
                            const float4* __restrict__ C0) {
    int i = blockIdx.x * blockDim.x + threadIdx.x; // 0 .. 1048575
    float4 w = Wx[i], m = mx[i];
    ((float4*)g_Wx)[i] = make_float4(w.x * m.x, w.y * m.y, w.z * m.z, w.w * m.w);
    w = Wh[i]; m = mh[i];
    ((float4*)g_Wh)[i] = make_float4(w.x * m.x, w.y * m.y, w.z * m.z, w.w * m.w);
    if (i < (BATCH * HDIM) / 4)
        ((float4*)g_C)[i] = C0[i];
}

// ---------------------------------------------------------------------------
// Phase 1: g_XW[tb][gh] = sum_i inputs[tb][i] * g_Wx[gh][i]
// Tile 128x128, BK=16, 256 threads, 8x8 micro-tile, FFMA2.
// A duplicated in SMEM so LDS.64 gives (a,a); B thread columns are
// {2*tx + 32*j} so b LDS.64 is stride-contiguous across the warp.
// ---------------------------------------------------------------------------
__global__ __launch_bounds__(256) void gemm_xw_kernel(const float* __restrict__ A) {
    __shared__ __align__(16) float As2[16][256]; // row m duplicated at [2m],[2m+1]
    __shared__ __align__(16) float Bs[16][128];

    const int tid = threadIdx.x;
    const int bm  = blockIdx.y * 128;
    const int bn  = blockIdx.x * 128;

    // loaders: each thread 2 float4 from A and 2 from B per K-slab
    const int lr = tid >> 1;          // 0..127 tile row
    const int lk = (tid & 1) * 4;     // 0 or 4
    const float* Ag = A    + (size_t)(bm + lr) * IDIM + lk;
    const float* Bg = g_Wx + (size_t)(bn + lr) * IDIM + lk;

    const int ty = tid >> 4;  // 0..15 -> rows ty*8 .. ty*8+7
    const int tx = tid & 15;  // cols {2*tx + 32*j}, j=0..3 (pairs)

    unsigned long long acc[8][4] = {};

    for (int k0 = 0; k0 < IDIM; k0 += 16) {
        float4 a0 = *(const float4*)(Ag + k0);
        float4 a1 = *(const float4*)(Ag + k0 + 8);
        float4 b0 = *(const float4*)(Bg + k0);
        float4 b1 = *(const float4*)(Bg + k0 + 8);
        __syncthreads();
        As2[lk + 0][2 * lr] = a0.x; As2[lk + 0][2 * lr + 1] = a0.x;
        As2[lk + 1][2 * lr] = a0.y; As2[lk + 1][2 * lr + 1] = a0.y;
        As2[lk + 2][2 * lr] = a0.z; As2[lk + 2][2 * lr + 1] = a0.z;
        As2[lk + 3][2 * lr] = a0.w; As2[lk + 3][2 * lr + 1] = a0.w;
        As2[lk + 8][2 * lr] = a1.x; As2[lk + 8][2 * lr + 1] = a1.x;
        As2[lk + 9][2 * lr] = a1.y; As2[lk + 9][2 * lr + 1] = a1.y;
        As2[lk +10][2 * lr] = a1.z; As2[lk +10][2 * lr + 1] = a1.z;
        As2[lk +11][2 * lr] = a1.w; As2[lk +11][2 * lr + 1] = a1.w;
        Bs[lk + 0][lr] = b0.x; Bs[lk + 1][lr] = b0.y;
        Bs[lk + 2][lr] = b0.z; Bs[lk + 3][lr] = b0.w;
        Bs[lk + 8][lr] = b1.x; Bs[lk + 9][lr] = b1.y;
        Bs[lk +10][lr] = b1.z; Bs[lk +11][lr] = b1.w;
        __syncthreads();

        #pragma unroll
        for (int kk = 0; kk < 16; ++kk) {
            unsigned long long a2[8], b2[4];
            #pragma unroll
            for (int i = 0; i < 8; ++i)
                a2[i] = *(const unsigned long long*)&As2[kk][2 * (ty * 8 + i)];
            #pragma unroll
            for (int j = 0; j < 4; ++j)
                b2[j] = *(const unsigned long long*)&Bs[kk][2 * tx + 32 * j];
            #pragma unroll
            for (int i = 0; i < 8; ++i)
                #pragma unroll
                for (int j = 0; j < 4; ++j)
                    ffma2(acc[i][j], a2[i], b2[j]);
        }
    }

    #pragma unroll
    for (int i = 0; i < 8; ++i) {
        float* crow = g_XW + (size_t)(bm + ty * 8 + i) * GDIM + bn;
        #pragma unroll
        for (int j = 0; j < 4; ++j)
            *(unsigned long long*)(crow + 2 * tx + 32 * j) = acc[i][j];
    }
}

// ---------------------------------------------------------------------------
// Phase 2: one fused LSTM step.
//   Block b covers h in [8*b, 8*b+8) for ALL 4 gates (32 W columns) and all
//   64 batches. GEMM vs Hprev, then add XW + bias, activations, C/H update.
// Grid 128 blocks x 128 threads. micro 4x4 (4 batches x 4 gates of one h).
// SMEM column mapping: c<16 -> (gate=c&1, hh=c>>1); c>=16 -> (gate=2+(c&1),
// hh=(c-16)>>1). Thread tx then owns cols {2tx,2tx+1,16+2tx,17+2tx} =
// gates (i,f,o,c) of h = h0+tx.
// ---------------------------------------------------------------------------
__global__ __launch_bounds__(128) void lstm_step_kernel(const float* __restrict__ Hprev,
                                                        const float* __restrict__ bias,
                                                        float* __restrict__ Hout,
                                                        int t) {
    __shared__ __align__(16) float As2[16][128]; // 64 batch rows duplicated
    __shared__ __align__(16) float Ws[16][32];

    const int tid = threadIdx.x;
    const int h0  = blockIdx.x * 8;

    // A loader: 64x16 tile, thread -> (row=tid>>1, k=(tid&1)*4), 2 float4
    const int lr  = tid >> 1;         // 0..63
    const int lka = (tid & 1) * 4;    // 0 or 4
    const float* Ag = Hprev + (size_t)lr * HDIM + lka;

    // W loader: 32x16 tile, thread -> (col=tid>>2, k=(tid&3)*4), 1 float4
    const int wc  = tid >> 2;         // 0..31 smem column
    const int lkw = (tid & 3) * 4;
    const int wg  = (wc < 16) ? (wc & 1) : 2 + (wc & 1);
    const int whh = (wc < 16) ? (wc >> 1) : ((wc - 16) >> 1);
    const float* Wg = g_Wh + (size_t)(wg * HDIM + h0 + whh) * HDIM + lkw;

    const int ty = tid >> 3;  // 0..15 -> batches ty*4 .. ty*4+3
    const int tx = tid & 7;   // h = h0 + tx

    unsigned long long acc[4][2] = {};

    for (int k0 = 0; k0 < HDIM; k0 += 16) {
        float4 a0 = *(const float4*)(Ag + k0);
        float4 a1 = *(const float4*)(Ag + k0 + 8);
        float4 w0 = *(const float4*)(Wg + k0);
        __syncthreads();
        As2[lka + 0][2 * lr] = a0.x; As2[lka + 0][2 * lr + 1] = a0.x;
        As2[lka + 1][2 * lr] = a0.y; As2[lka + 1][2 * lr + 1] = a0.y;
        As2[lka + 2][2 * lr] = a0.z; As2[lka + 2][2 * lr + 1] = a0.z;
        As2[lka + 3][2 * lr] = a0.w; As2[lka + 3][2 * lr + 1] = a0.w;
        As2[lka + 8][2 * lr] = a1.x; As2[lka + 8][2 * lr + 1] = a1.x;
        As2[lka + 9][2 * lr] = a1.y; As2[lka + 9][2 * lr + 1] = a1.y;
        As2[lka +10][2 * lr] = a1.z; As2[lka +10][2 * lr + 1] = a1.z;
        As2[lka +11][2 * lr] = a1.w; As2[lka +11][2 * lr + 1] = a1.w;
        Ws[lkw + 0][wc] = w0.x; Ws[lkw + 1][wc] = w0.y;
        Ws[lkw + 2][wc] = w0.z; Ws[lkw + 3][wc] = w0.w;
        __syncthreads();

        #pragma unroll
        for (int kk = 0; kk < 16; ++kk) {
            unsigned long long a2[4], b2[2];
            #pragma unroll
            for (int i = 0; i < 4; ++i)
                a2[i] = *(const unsigned long long*)&As2[kk][2 * (ty * 4 + i)];
            b2[0] = *(const unsigned long long*)&Ws[kk][2 * tx];
            b2[1] = *(const unsigned long long*)&Ws[kk][16 + 2 * tx];
            #pragma unroll
            for (int i = 0; i < 4; ++i) {
                ffma2(acc[i][0], a2[i], b2[0]);
                ffma2(acc[i][1], a2[i], b2[1]);
            }
        }
    }

    // Fused epilogue: gates -> activations -> C/H update -> output
    const int h = h0 + tx;
    const float bi = bias[h];
    const float bf = bias[HDIM + h];
    const float bo = bias[2 * HDIM + h];
    const float bc = bias[3 * HDIM + h];
    const float* xw = g_XW + (size_t)t * BATCH * GDIM;

    #pragma unroll
    for (int i = 0; i < 4; ++i) {
        const int b = ty * 4 + i;
        float2 g01 = unpack2(acc[i][0]); // (i_gate, f_gate) pre-act partials
        float2 g23 = unpack2(acc[i][1]); // (o_gate, c_gate)
        const float* xwr = xw + (size_t)b * GDIM;
        float pi = g01.x + xwr[h]             + bi;
        float pf = g01.y + xwr[HDIM + h]      + bf;
        float po = g23.x + xwr[2 * HDIM + h]  + bo;
        float pc = g23.y + xwr[3 * HDIM + h]  + bc;
        float Ig = 1.0f / (1.0f + expf(-pi));
        float Fg = 1.0f / (1.0f + expf(-pf));
        float Og = 1.0f / (1.0f + expf(-po));
        float Ct = tanhf(pc);
        float cold = g_C[b * HDIM + h];
        float cnew = Fg * cold + Ig * Ct;
        g_C[b * HDIM + h]  = cnew;
        Hout[b * HDIM + h] = Og * tanhf(cnew);
    }
}

// ---------------------------------------------------------------------------
// Launch: prep -> big XW GEMM -> 256 fused sequential steps.
// H state lives in d_out rows (step t reads out[t-1]); C lives in g_C.
// All launches on the capturing (default) stream; no allocs, no syncs.
// ---------------------------------------------------------------------------
extern "C" void kernel_launch(void* const* d_in, const int* in_sizes, int n_in,
                              void* d_out, int out_size) {
    (void)in_sizes; (void)n_in; (void)out_size;
    const float* inputs = (const float*)d_in[0]; // (T, B, I)
    const float* W_x    = (const float*)d_in[1]; // (4, H, I)
    const float* W_h    = (const float*)d_in[2]; // (4, H, H)
    const float* bias   = (const float*)d_in[3]; // (4, H)
    const float* mask_x = (const float*)d_in[4]; // (4, H, I)
    const float* mask_h = (const float*)d_in[5]; // (4, H, H)
    const float* H0     = (const float*)d_in[6]; // (B, H)
    const float* C0     = (const float*)d_in[7]; // (B, H)
    float* out = (float*)d_out;                  // (T, B, H)

    // 1) mask weights + init C  (4M float4 elements -> 4096 x 256 threads)
    prep_kernel<<<4096, 256>>>((const float4*)W_x, (const float4*)mask_x,
                               (const float4*)W_h, (const float4*)mask_h,
                               (const float4*)C0);

    // 2) XW = inputs @ Wx^T : [16384 x 4096], K=1024
    gemm_xw_kernel<<<dim3(GDIM / 128, TBROWS / 128), 256>>>(inputs);

    // 3) 256 fused recurrent steps
    for (int t = 0; t < T_STEPS; ++t) {
        const float* Hprev = (t == 0) ? H0 : out + (size_t)(t - 1) * BATCH * HDIM;
        lstm_step_kernel<<<HDIM / 8, 128>>>(Hprev, bias,
                                            out + (size_t)t * BATCH * HDIM, t);
    }
}

// round 3
// speedup vs baseline: 2.5534x; 2.5534x over previous
#include <cuda_runtime.h>
#include <cstdint>
#include <math.h>

// Problem constants
#define T_STEPS 256
#define BATCH   64
#define IDIM    1024
#define HDIM    1024
#define GDIM    4096
#define TBROWS  (T_STEPS * BATCH)

// ---------------------------------------------------------------------------
// Device scratch
// ---------------------------------------------------------------------------
__device__ __align__(16) float    g_Wx[(size_t)GDIM * IDIM];      // masked W_x fp32
__device__ __align__(16) float    g_XW[(size_t)TBROWS * GDIM];    // X @ Wx^T fp32, [tb][g*1024+h]
__device__ __align__(16) float    g_C [(size_t)BATCH * HDIM];     // cell state
__device__ __align__(16) uint32_t g_Wp[(size_t)HDIM * GDIM];      // tf32 Wh, [k][col'] col'=nb*32+g*8+j
__device__ __align__(16) uint32_t g_Ht[2][(size_t)BATCH * HDIM];  // tf32 H ping-pong, [b][h]

// ---------------------------------------------------------------------------
// Helpers
// ---------------------------------------------------------------------------
__device__ __forceinline__ void ffma2(unsigned long long &acc,
                                      unsigned long long a,
                                      unsigned long long b) {
    asm("fma.rn.f32x2 %0, %1, %2, %0;" : "+l"(acc) : "l"(a), "l"(b));
}

__device__ __forceinline__ uint32_t smem_u32(const void* p) {
    uint32_t r;
    asm("{ .reg .u64 t; cvta.to.shared.u64 t, %1; cvt.u32.u64 %0, t; }" : "=r"(r) : "l"(p));
    return r;
}
__device__ __forceinline__ void cp16(uint32_t dst, const void* src) {
    asm volatile("cp.async.cg.shared.global [%0], [%1], 16;" :: "r"(dst), "l"(src));
}
#define CP_COMMIT() asm volatile("cp.async.commit_group;")
#define CP_WAIT(n)  asm volatile("cp.async.wait_group %0;" :: "n"(n))

__device__ __forceinline__ uint32_t f2tf32(float v) {
    uint32_t r; asm("cvt.rna.tf32.f32 %0, %1;" : "=r"(r) : "f"(v));
    return r;
}

// m16n8k8 tf32 HMMA (baseline PTX, works on compute_103)
__device__ __forceinline__ void mma_tf32(float* d, const uint32_t* a, uint32_t b0, uint32_t b1) {
    asm volatile(
        "mma.sync.aligned.m16n8k8.row.col.f32.tf32.tf32.f32 "
        "{%0,%1,%2,%3}, {%4,%5,%6,%7}, {%8,%9}, {%0,%1,%2,%3};"
        : "+f"(d[0]), "+f"(d[1]), "+f"(d[2]), "+f"(d[3])
        : "r"(a[0]), "r"(a[1]), "r"(a[2]), "r"(a[3]), "r"(b0), "r"(b1));
}

// ---------------------------------------------------------------------------
// Prep 1: mask W_x (fp32), init C
// ---------------------------------------------------------------------------
__global__ void prep_wx_kernel(const float4* __restrict__ Wx, const float4* __restrict__ mx,
                               const float4* __restrict__ C0) {
    int i = blockIdx.x * blockDim.x + threadIdx.x; // < 1048576
    float4 w = Wx[i], m = mx[i];
    ((float4*)g_Wx)[i] = make_float4(w.x * m.x, w.y * m.y, w.z * m.z, w.w * m.w);
    if (i < (BATCH * HDIM) / 4)
        ((float4*)g_C)[i] = C0[i];
}

// ---------------------------------------------------------------------------
// Prep 2: W_h -> masked tf32, transposed to [k][col'], col' = nb*32 + g*8 + j,
// where h = nb*8 + j. Writes coalesced.
// ---------------------------------------------------------------------------
__global__ void prep_wp_kernel(const float* __restrict__ Wh, const float* __restrict__ mh) {
    const int i   = blockIdx.x * 256 + threadIdx.x;  // < 4M, i = k*4096 + col
    const int col = i & 4095;
    const int k   = i >> 12;
    const int g   = (col >> 3) & 3;
    const int h   = ((col >> 5) << 3) + (col & 7);
    const size_t src = ((size_t)g << 20) + ((size_t)h << 10) + k;
    g_Wp[i] = f2tf32(Wh[src] * mh[src]);
}

// ---------------------------------------------------------------------------
// Prep 3: H0 -> tf32 image, buffer 0, plain [b][h]
// ---------------------------------------------------------------------------
__global__ void prep_h0_kernel(const float* __restrict__ H0) {
    const int i = blockIdx.x * 256 + threadIdx.x;   // < 65536
    g_Ht[0][i] = f2tf32(H0[i]);
}

// ---------------------------------------------------------------------------
// Phase 1: g_XW = inputs @ Wx^T  (fp32 FFMA2, unchanged from passing round)
// ---------------------------------------------------------------------------
__global__ __launch_bounds__(256) void gemm_xw_kernel(const float* __restrict__ A) {
    __shared__ __align__(16) float As2[16][256];
    __shared__ __align__(16) float Bs[16][128];

    const int tid = threadIdx.x;
    const int bm  = blockIdx.y * 128;
    const int bn  = blockIdx.x * 128;

    const int lr = tid >> 1;
    const int lk = (tid & 1) * 4;
    const float* Ag = A    + (size_t)(bm + lr) * IDIM + lk;
    const float* Bg = g_Wx + (size_t)(bn + lr) * IDIM + lk;

    const int ty = tid >> 4;
    const int tx = tid & 15;

    unsigned long long acc[8][4] = {};

    for (int k0 = 0; k0 < IDIM; k0 += 16) {
        float4 a0 = *(const float4*)(Ag + k0);
        float4 a1 = *(const float4*)(Ag + k0 + 8);
        float4 b0 = *(const float4*)(Bg + k0);
        float4 b1 = *(const float4*)(Bg + k0 + 8);
        __syncthreads();
        As2[lk + 0][2 * lr] = a0.x; As2[lk + 0][2 * lr + 1] = a0.x;
        As2[lk + 1][2 * lr] = a0.y; As2[lk + 1][2 * lr + 1] = a0.y;
        As2[lk + 2][2 * lr] = a0.z; As2[lk + 2][2 * lr + 1] = a0.z;
        As2[lk + 3][2 * lr] = a0.w; As2[lk + 3][2 * lr + 1] = a0.w;
        As2[lk + 8][2 * lr] = a1.x; As2[lk + 8][2 * lr + 1] = a1.x;
        As2[lk + 9][2 * lr] = a1.y; As2[lk + 9][2 * lr + 1] = a1.y;
        As2[lk +10][2 * lr] = a1.z; As2[lk +10][2 * lr + 1] = a1.z;
        As2[lk +11][2 * lr] = a1.w; As2[lk +11][2 * lr + 1] = a1.w;
        Bs[lk + 0][lr] = b0.x; Bs[lk + 1][lr] = b0.y;
        Bs[lk + 2][lr] = b0.z; Bs[lk + 3][lr] = b0.w;
        Bs[lk + 8][lr] = b1.x; Bs[lk + 9][lr] = b1.y;
        Bs[lk +10][lr] = b1.z; Bs[lk +11][lr] = b1.w;
        __syncthreads();

        #pragma unroll
        for (int kk = 0; kk < 16; ++kk) {
            unsigned long long a2[8], b2[4];
            #pragma unroll
            for (int i = 0; i < 8; ++i)
                a2[i] = *(const unsigned long long*)&As2[kk][2 * (ty * 8 + i)];
            #pragma unroll
            for (int j = 0; j < 4; ++j)
                b2[j] = *(const unsigned long long*)&Bs[kk][2 * tx + 32 * j];
            #pragma unroll
            for (int i = 0; i < 8; ++i)
                #pragma unroll
                for (int j = 0; j < 4; ++j)
                    ffma2(acc[i][j], a2[i], b2[j]);
        }
    }

    #pragma unroll
    for (int i = 0; i < 8; ++i) {
        float* crow = g_XW + (size_t)(bm + ty * 8 + i) * GDIM + bn;
        #pragma unroll
        for (int j = 0; j < 4; ++j)
            *(unsigned long long*)(crow + 2 * tx + 32 * j) = acc[i][j];
    }
}

// ---------------------------------------------------------------------------
// Phase 2: one LSTM step via mma.sync tf32.
//  grid 128 CTAs x 128 threads. CTA nb owns 32 gate-columns col'=nb*32+g*8+j
//  (h = nb*8+j, all 4 gates) for all 64 batches.
//  A = H[64,1024] (tf32 image), B = Wp^T slice. K pipelined in chunks of 32
//  with a 3-stage cp.async ring. Warp w computes batch rows [16w,16w+16).
//  D-fragment: thread owns all 4 gates of (b, h) pairs -> register-local
//  epilogue (activations, C/H update, H tf32 image for next step).
// ---------------------------------------------------------------------------
#define NSTG 3
__global__ __launch_bounds__(128) void lstm_step_mma(const float* __restrict__ bias,
                                                     float* __restrict__ Hout,
                                                     int t) {
    __shared__ __align__(16) float As[NSTG][64][36];   // [m][k], pad 36
    __shared__ __align__(16) float Bs[NSTG][32][40];   // [k][n], pad 40

    const int tid  = threadIdx.x;
    const int w    = tid >> 5;
    const int lane = tid & 31;
    const int tq   = lane >> 2;      // 0..7
    const int tr   = lane & 3;       // 0..3
    const int nb   = blockIdx.x;

    const uint32_t* Ht = g_Ht[t & 1];
    const uint32_t* Wp = g_Wp + nb * 32;

    const uint32_t sA = smem_u32(&As[0][0][0]);
    const uint32_t sB = smem_u32(&Bs[0][0][0]);

    // per-thread cp.async source/dst offsets
    // A: e = tid + 128*j (j<4): m = e>>3, c4 = e&7
    // B: e = tid + 128*j (j<2): kr = e>>3, c4 = e&7
    #define LOAD_CHUNK(kc_, st_)                                              \
    {                                                                         \
        _Pragma("unroll")                                                     \
        for (int j_ = 0; j_ < 4; ++j_) {                                      \
            int e_ = tid + 128 * j_;                                          \
            int m_ = e_ >> 3, c_ = e_ & 7;                                    \
            cp16(sA + (st_) * 9216u + m_ * 144u + c_ * 16u,                   \
                 Ht + m_ * 1024 + (kc_) * 32 + c_ * 4);                       \
        }                                                                     \
        _Pragma("unroll")                                                     \
        for (int j_ = 0; j_ < 2; ++j_) {                                      \
            int e_ = tid + 128 * j_;                                          \
            int k_ = e_ >> 3, c_ = e_ & 7;                                    \
            cp16(sB + (st_) * 5120u + k_ * 160u + c_ * 16u,                   \
                 Wp + ((size_t)((kc_) * 32 + k_) << 12) + c_ * 4);            \
        }                                                                     \
        CP_COMMIT();                                                          \
    }

    float acc[4][4] = {};   // [gate][c]

    LOAD_CHUNK(0, 0);
    LOAD_CHUNK(1, 1);

    for (int kc = 0; kc < 32; ++kc) {
        const int st = kc % NSTG;
        if (kc + 2 < 32) {
            LOAD_CHUNK(kc + 2, (kc + 2) % NSTG);
            CP_WAIT(2);
        } else {
            CP_WAIT(0);
        }
        __syncthreads();

        const float (*Ab)[36] = As[st];
        const float (*Bb)[40] = Bs[st];
        #pragma unroll
        for (int ks = 0; ks < 4; ++ks) {
            const int k0 = ks * 8;
            uint32_t a[4];
            a[0] = __float_as_uint(Ab[w * 16 + tq    ][k0 + tr    ]);
            a[1] = __float_as_uint(Ab[w * 16 + tq + 8][k0 + tr    ]);
            a[2] = __float_as_uint(Ab[w * 16 + tq    ][k0 + tr + 4]);
            a[3] = __float_as_uint(Ab[w * 16 + tq + 8][k0 + tr + 4]);
            #pragma unroll
            for (int g = 0; g < 4; ++g) {
                uint32_t b0 = __float_as_uint(Bb[k0 + tr    ][g * 8 + tq]);
                uint32_t b1 = __float_as_uint(Bb[k0 + tr + 4][g * 8 + tq]);
                mma_tf32(acc[g], a, b0, b1);
            }
        }
        __syncthreads();
    }

    // Epilogue: thread holds gates for (b, h) at:
    //   c=0: b=16w+tq,   j=2*tr ;  c=1: b=16w+tq,   j=2*tr+1
    //   c=2: b=16w+tq+8, j=2*tr ;  c=3: b=16w+tq+8, j=2*tr+1
    const float* xw = g_XW + ((size_t)t << 18);
    uint32_t* Hw = g_Ht[(t + 1) & 1];

    #pragma unroll
    for (int c = 0; c < 4; ++c) {
        const int b = 16 * w + tq + ((c >> 1) << 3);
        const int h = nb * 8 + 2 * tr + (c & 1);
        const float* xr = xw + ((size_t)b << 12);
        float pi = acc[0][c] + xr[h]        + bias[h];
        float pf = acc[1][c] + xr[1024 + h] + bias[1024 + h];
        float po = acc[2][c] + xr[2048 + h] + bias[2048 + h];
        float pc = acc[3][c] + xr[3072 + h] + bias[3072 + h];
        float Ig = 1.0f / (1.0f + __expf(-pi));
        float Fg = 1.0f / (1.0f + __expf(-pf));
        float Og = 1.0f / (1.0f + __expf(-po));
        float Ct = tanhf(pc);
        float cold = g_C[(b << 10) + h];
        float cn = Fg * cold + Ig * Ct;
        g_C[(b << 10) + h] = cn;
        float Hn = Og * tanhf(cn);
        Hout[(b << 10) + h] = Hn;
        Hw[(b << 10) + h] = f2tf32(Hn);
    }
    #undef LOAD_CHUNK
}

// ---------------------------------------------------------------------------
// Launch
// ---------------------------------------------------------------------------
extern "C" void kernel_launch(void* const* d_in, const int* in_sizes, int n_in,
                              void* d_out, int out_size) {
    (void)in_sizes; (void)n_in; (void)out_size;
    const float* inputs = (const float*)d_in[0];
    const float* W_x    = (const float*)d_in[1];
    const float* W_h    = (const float*)d_in[2];
    const float* bias   = (const float*)d_in[3];
    const float* mask_x = (const float*)d_in[4];
    const float* mask_h = (const float*)d_in[5];
    const float* H0     = (const float*)d_in[6];
    const float* C0     = (const float*)d_in[7];
    float* out = (float*)d_out;

    prep_wx_kernel<<<4096, 256>>>((const float4*)W_x, (const float4*)mask_x,
                                  (const float4*)C0);
    prep_wp_kernel<<<16384, 256>>>(W_h, mask_h);
    prep_h0_kernel<<<256, 256>>>(H0);

    gemm_xw_kernel<<<dim3(GDIM / 128, TBROWS / 128), 256>>>(inputs);

    for (int t = 0; t < T_STEPS; ++t)
        lstm_step_mma<<<128, 128>>>(bias, out + (size_t)t * BATCH * HDIM, t);
}

// round 6
// speedup vs baseline: 3.6067x; 1.4125x over previous
#include <cuda_runtime.h>
#include <cstdint>
#include <math.h>

// Problem constants
#define T_STEPS 256
#define BATCH   64
#define IDIM    1024
#define HDIM    1024
#define GDIM    4096
#define TBROWS  (T_STEPS * BATCH)

// ---------------------------------------------------------------------------
// Device scratch
// ---------------------------------------------------------------------------
__device__ __align__(16) float    g_XW[(size_t)TBROWS * GDIM];    // X @ Wx^T fp32, [tb][g*1024+h]
__device__ __align__(16) float    g_C [(size_t)BATCH * HDIM];     // cell state
__device__ __align__(16) uint32_t g_Wxp[(size_t)IDIM * GDIM];     // tf32 Wx^T, [k][gh]
__device__ __align__(16) uint32_t g_Wp[(size_t)HDIM * GDIM];      // tf32 Wh, [k][col'] col'=nb*32+g*8+j
__device__ __align__(16) uint32_t g_Ht[2][(size_t)BATCH * HDIM];  // tf32 H ping-pong, [b][h]

// ---------------------------------------------------------------------------
// Helpers
// ---------------------------------------------------------------------------
__device__ __forceinline__ uint32_t smem_u32(const void* p) {
    uint32_t r;
    asm("{ .reg .u64 t; cvta.to.shared.u64 t, %1; cvt.u32.u64 %0, t; }" : "=r"(r) : "l"(p));
    return r;
}
__device__ __forceinline__ void cp16(uint32_t dst, const void* src) {
    asm volatile("cp.async.cg.shared.global [%0], [%1], 16;" :: "r"(dst), "l"(src));
}
#define CP_COMMIT() asm volatile("cp.async.commit_group;")
#define CP_WAIT(n)  asm volatile("cp.async.wait_group %0;" :: "n"(n))

__device__ __forceinline__ uint32_t f2tf32(float v) {
    uint32_t r; asm("cvt.rna.tf32.f32 %0, %1;" : "=r"(r) : "f"(v));
    return r;
}

// m16n8k8 tf32 HMMA (baseline PTX, works on compute_103)
__device__ __forceinline__ void mma_tf32(float* d, const uint32_t* a, uint32_t b0, uint32_t b1) {
    asm volatile(
        "mma.sync.aligned.m16n8k8.row.col.f32.tf32.tf32.f32 "
        "{%0,%1,%2,%3}, {%4,%5,%6,%7}, {%8,%9}, {%0,%1,%2,%3};"
        : "+f"(d[0]), "+f"(d[1]), "+f"(d[2]), "+f"(d[3])
        : "r"(a[0]), "r"(a[1]), "r"(a[2]), "r"(a[3]), "r"(b0), "r"(b1));
}

// ---------------------------------------------------------------------------
// Prep 1: W_x -> masked tf32, transposed to [k][gh]  (gh = g*1024+h standard)
// ---------------------------------------------------------------------------
__global__ void prep_wxp_kernel(const float* __restrict__ Wx, const float* __restrict__ mx) {
    const int i   = blockIdx.x * 256 + threadIdx.x;  // i = k*4096 + col
    const int col = i & 4095;
    const int k   = i >> 12;
    const size_t src = ((size_t)col << 10) + k;
    g_Wxp[i] = f2tf32(Wx[src] * mx[src]);
}

// ---------------------------------------------------------------------------
// Prep 2: W_h -> masked tf32, transposed to [k][col'], col' = nb*32 + g*8 + j,
// where h = nb*8 + j.
// ---------------------------------------------------------------------------
__global__ void prep_wp_kernel(const float* __restrict__ Wh, const float* __restrict__ mh) {
    const int i   = blockIdx.x * 256 + threadIdx.x;
    const int col = i & 4095;
    const int k   = i >> 12;
    const int g   = (col >> 3) & 3;
    const int h   = ((col >> 5) << 3) + (col & 7);
    const size_t src = ((size_t)g << 20) + ((size_t)h << 10) + k;
    g_Wp[i] = f2tf32(Wh[src] * mh[src]);
}

// ---------------------------------------------------------------------------
// Prep 3: H0 -> tf32 image (buffer 0); C0 -> g_C
// ---------------------------------------------------------------------------
__global__ void prep_h0c_kernel(const float* __restrict__ H0, const float* __restrict__ C0) {
    const int i = blockIdx.x * 256 + threadIdx.x;   // < 65536
    g_Ht[0][i] = f2tf32(H0[i]);
    g_C[i] = C0[i];
}

// ---------------------------------------------------------------------------
// Phase 1: g_XW = inputs @ Wxp  via tf32 mma.sync.
//  M=16384, N=4096, K=1024. CTA tile 128x128, BK=32, 256 thr (8 warps 2x4),
//  warp tile 64x32, 2-stage cp.async. A = raw fp32 (tf32 truncation).
//  smem floats: As[2][128][36] @0 ; Bs[2][32][132] @9216
// ---------------------------------------------------------------------------
#define XW_SMEM_BYTES ((9216 + 8448) * 4)
__global__ __launch_bounds__(256) void gemm_xw_mma(const float* __restrict__ A) {
    extern __shared__ __align__(16) float dsm[];
    const int tid  = threadIdx.x;
    const int w    = tid >> 5;
    const int lane = tid & 31;
    const int tq   = lane >> 2;
    const int tr   = lane & 3;
    const int bm   = blockIdx.y * 128;
    const int bn   = blockIdx.x * 128;
    const int wm   = (w >> 2) * 64;
    const int wn   = (w & 3) * 32;

    const uint32_t sA = smem_u32(dsm);
    const uint32_t sB = sA + 9216u * 4u;

    #define XW_LOAD(kc_, st_)                                                 \
    {                                                                         \
        _Pragma("unroll")                                                     \
        for (int j_ = 0; j_ < 4; ++j_) {                                      \
            int e_ = tid + 256 * j_;                                          \
            int m_ = e_ >> 3, c_ = e_ & 7;                                    \
            cp16(sA + (st_) * 18432u + m_ * 144u + c_ * 16u,                  \
                 A + (size_t)(bm + m_) * 1024 + (kc_) * 32 + c_ * 4);         \
        }                                                                     \
        _Pragma("unroll")                                                     \
        for (int j_ = 0; j_ < 4; ++j_) {                                      \
            int e_ = tid + 256 * j_;                                          \
            int k_ = e_ >> 5, c_ = e_ & 31;                                   \
            cp16(sB + (st_) * 16896u + k_ * 528u + c_ * 16u,                  \
                 g_Wxp + ((size_t)((kc_) * 32 + k_) << 12) + bn + c_ * 4);    \
        }                                                                     \
        CP_COMMIT();                                                          \
    }

    float acc[4][4][4] = {};

    XW_LOAD(0, 0);

    for (int kc = 0; kc < 32; ++kc) {
        const int st = kc & 1;
        if (kc + 1 < 32) { XW_LOAD(kc + 1, st ^ 1); CP_WAIT(1); }
        else             { CP_WAIT(0); }
        __syncthreads();

        const float* Ab = dsm + st * 4608;           // [128][36]
        const float* Bb = dsm + 9216 + st * 4224;    // [32][132]
        #pragma unroll
        for (int ks = 0; ks < 4; ++ks) {
            const int k0 = ks * 8;
            uint32_t a[4][4];
            #pragma unroll
            for (int mi = 0; mi < 4; ++mi) {
                const int rm = wm + mi * 16;
                a[mi][0] = __float_as_uint(Ab[(rm + tq    ) * 36 + k0 + tr    ]);
                a[mi][1] = __float_as_uint(Ab[(rm + tq + 8) * 36 + k0 + tr    ]);
                a[mi][2] = __float_as_uint(Ab[(rm + tq    ) * 36 + k0 + tr + 4]);
                a[mi][3] = __float_as_uint(Ab[(rm + tq + 8) * 36 + k0 + tr + 4]);
            }
            #pragma unroll
            for (int ni = 0; ni < 4; ++ni) {
                uint32_t b0 = __float_as_uint(Bb[(k0 + tr    ) * 132 + wn + ni * 8 + tq]);
                uint32_t b1 = __float_as_uint(Bb[(k0 + tr + 4) * 132 + wn + ni * 8 + tq]);
                #pragma unroll
                for (int mi = 0; mi < 4; ++mi)
                    mma_tf32(acc[mi][ni], a[mi], b0, b1);
            }
        }
        __syncthreads();
    }
    #undef XW_LOAD

    #pragma unroll
    for (int mi = 0; mi < 4; ++mi) {
        const int r0 = bm + wm + mi * 16 + tq;
        #pragma unroll
        for (int ni = 0; ni < 4; ++ni) {
            const int cn = bn + wn + ni * 8 + 2 * tr;
            *(float2*)(g_XW + (size_t)r0 * GDIM + cn) =
                make_float2(acc[mi][ni][0], acc[mi][ni][1]);
            *(float2*)(g_XW + (size_t)(r0 + 8) * GDIM + cn) =
                make_float2(acc[mi][ni][2], acc[mi][ni][3]);
        }
    }
}

// ---------------------------------------------------------------------------
// Phase 2: one LSTM step, split-K tf32 mma.
//  128 CTAs x 256 thr. CTA nb owns cols col'=nb*32+g*8+j (h=nb*8+j, 4 gates).
//  Warp w: kh=w>>2 (K half), wb=w&3 (batch rows 16*wb). Chunk = 64 k, 16
//  chunks, 3-stage cp.async ring. smem reduce of K halves, then register
//  epilogue.  smem floats: As[3][64][68] @0 ; Bs[3][64][36] @13056
// ---------------------------------------------------------------------------
#define ST_SMEM_BYTES ((13056 + 6912) * 4)
__global__ __launch_bounds__(256) void lstm_step_mma2(const float* __restrict__ bias,
                                                      float* __restrict__ Hout,
                                                      int t) {
    extern __shared__ __align__(16) float dsm[];
    const int tid  = threadIdx.x;
    const int w    = tid >> 5;
    const int lane = tid & 31;
    const int tq   = lane >> 2;
    const int tr   = lane & 3;
    const int nb   = blockIdx.x;
    const int wb   = w & 3;
    const int kh   = w >> 2;

    const uint32_t* Ht = g_Ht[t & 1];
    const uint32_t* Wp = g_Wp + nb * 32;

    const uint32_t sA = smem_u32(dsm);
    const uint32_t sB = sA + 13056u * 4u;

    #define ST_LOAD(kc_, st_)                                                 \
    {                                                                         \
        _Pragma("unroll")                                                     \
        for (int j_ = 0; j_ < 4; ++j_) {                                      \
            int e_ = tid + 256 * j_;                                          \
            int m_ = e_ >> 4, c_ = e_ & 15;                                   \
            cp16(sA + (st_) * 17408u + m_ * 272u + c_ * 16u,                  \
                 Ht + m_ * 1024 + (kc_) * 64 + c_ * 4);                       \
        }                                                                     \
        _Pragma("unroll")                                                     \
        for (int j_ = 0; j_ < 2; ++j_) {                                      \
            int e_ = tid + 256 * j_;                                          \
            int k_ = e_ >> 3, c_ = e_ & 7;                                    \
            cp16(sB + (st_) * 9216u + k_ * 144u + c_ * 16u,                   \
                 Wp + ((size_t)((kc_) * 64 + k_) << 12) + c_ * 4);            \
        }                                                                     \
        CP_COMMIT();                                                          \
    }

    float acc[4][4] = {};   // [gate][c]

    ST_LOAD(0, 0);
    ST_LOAD(1, 1);

    for (int kc = 0; kc < 16; ++kc) {
        const int st = kc % 3;
        if (kc + 2 < 16) { ST_LOAD(kc + 2, (kc + 2) % 3); CP_WAIT(2); }
        else             { CP_WAIT(0); }
        __syncthreads();

        const float* Ab = dsm + st * 4352;           // [64][68]
        const float* Bb = dsm + 13056 + st * 2304;   // [64][36]
        #pragma unroll
        for (int ks = 0; ks < 4; ++ks) {
            const int k0 = kh * 32 + ks * 8;
            uint32_t a[4];
            a[0] = __float_as_uint(Ab[(16 * wb + tq    ) * 68 + k0 + tr    ]);
            a[1] = __float_as_uint(Ab[(16 * wb + tq + 8) * 68 + k0 + tr    ]);
            a[2] = __float_as_uint(Ab[(16 * wb + tq    ) * 68 + k0 + tr + 4]);
            a[3] = __float_as_uint(Ab[(16 * wb + tq + 8) * 68 + k0 + tr + 4]);
            #pragma unroll
            for (int g = 0; g < 4; ++g) {
                uint32_t b0 = __float_as_uint(Bb[(k0 + tr    ) * 36 + g * 8 + tq]);
                uint32_t b1 = __float_as_uint(Bb[(k0 + tr + 4) * 36 + g * 8 + tq]);
                mma_tf32(acc[g], a, b0, b1);
            }
        }
        __syncthreads();
    }
    #undef ST_LOAD

    // K-half reduction through smem (aliases As stage 0; mainloop is done)
    const int ridx = ((wb * 32 + lane) << 4);
    if (kh == 1) {
        #pragma unroll
        for (int g = 0; g < 4; ++g)
            #pragma unroll
            for (int c = 0; c < 4; ++c)
                dsm[ridx + g * 4 + c] = acc[g][c];
    }
    __syncthreads();

    if (kh == 0) {
        #pragma unroll
        for (int g = 0; g < 4; ++g)
            #pragma unroll
            for (int c = 0; c < 4; ++c)
                acc[g][c] += dsm[ridx + g * 4 + c];

        // Epilogue: c=0: (b=16wb+tq,   j=2tr); c=1: +1; c=2: (b+8, 2tr); c=3: +1
        const float* xw = g_XW + ((size_t)t << 18);
        uint32_t* Hw = g_Ht[(t + 1) & 1];

        #pragma unroll
        for (int c = 0; c < 4; ++c) {
            const int b = 16 * wb + tq + ((c >> 1) << 3);
            const int h = nb * 8 + 2 * tr + (c & 1);
            const float* xr = xw + ((size_t)b << 12);
            float pi = acc[0][c] + xr[h]        + bias[h];
            float pf = acc[1][c] + xr[1024 + h] + bias[1024 + h];
            float po = acc[2][c] + xr[2048 + h] + bias[2048 + h];
            float pc = acc[3][c] + xr[3072 + h] + bias[3072 + h];
            float Ig = 1.0f / (1.0f + __expf(-pi));
            float Fg = 1.0f / (1.0f + __expf(-pf));
            float Og = 1.0f / (1.0f + __expf(-po));
            float Ct = tanhf(pc);
            float cold = g_C[(b << 10) + h];
            float cn = Fg * cold + Ig * Ct;
            g_C[(b << 10) + h] = cn;
            float Hn = Og * tanhf(cn);
            Hout[(b << 10) + h] = Hn;
            Hw[(b << 10) + h] = f2tf32(Hn);
        }
    }
}

// ---------------------------------------------------------------------------
// Launch
// ---------------------------------------------------------------------------
extern "C" void kernel_launch(void* const* d_in, const int* in_sizes, int n_in,
                              void* d_out, int out_size) {
    (void)in_sizes; (void)n_in; (void)out_size;
    const float* inputs = (const float*)d_in[0];
    const float* W_x    = (const float*)d_in[1];
    const float* W_h    = (const float*)d_in[2];
    const float* bias   = (const float*)d_in[3];
    const float* mask_x = (const float*)d_in[4];
    const float* mask_h = (const float*)d_in[5];
    const float* H0     = (const float*)d_in[6];
    const float* C0     = (const float*)d_in[7];
    float* out = (float*)d_out;

    cudaFuncSetAttribute(gemm_xw_mma,
                         cudaFuncAttributeMaxDynamicSharedMemorySize, XW_SMEM_BYTES);
    cudaFuncSetAttribute(lstm_step_mma2,
                         cudaFuncAttributeMaxDynamicSharedMemorySize, ST_SMEM_BYTES);

    prep_wxp_kernel<<<16384, 256>>>(W_x, mask_x);
    prep_wp_kernel <<<16384, 256>>>(W_h, mask_h);
    prep_h0c_kernel<<<256, 256>>>(H0, C0);

    gemm_xw_mma<<<dim3(GDIM / 128, TBROWS / 128), 256, XW_SMEM_BYTES>>>(inputs);

    for (int t = 0; t < T_STEPS; ++t)
        lstm_step_mma2<<<128, 256, ST_SMEM_BYTES>>>(bias,
                                                    out + (size_t)t * BATCH * HDIM, t);
}

// round 7
// speedup vs baseline: 3.8112x; 1.0567x over previous
#include <cuda_runtime.h>
#include <cstdint>
#include <math.h>

// Problem constants
#define T_STEPS 256
#define BATCH   64
#define IDIM    1024
#define HDIM    1024
#define GDIM    4096
#define TBROWS  (T_STEPS * BATCH)
#define NCTA    128

// ---------------------------------------------------------------------------
// Device scratch
// ---------------------------------------------------------------------------
__device__ __align__(16) float    g_XW[(size_t)TBROWS * GDIM];    // X @ Wx^T fp32, [tb][g*1024+h]
__device__ __align__(16) uint32_t g_Wxp[(size_t)IDIM * GDIM];     // tf32 Wx^T, [k][gh]
__device__ __align__(16) uint32_t g_Wp[(size_t)HDIM * GDIM];      // tf32 Wh, [k][col'] col'=nb*32+g*8+j
__device__ __align__(16) uint32_t g_Ht[2][(size_t)BATCH * HDIM];  // tf32 H ping-pong, [b][h]
__device__ int          g_cnt;                                    // grid barrier counter
__device__ volatile int g_gen;                                    // grid barrier generation

// ---------------------------------------------------------------------------
// Helpers
// ---------------------------------------------------------------------------
__device__ __forceinline__ uint32_t smem_u32(const void* p) {
    uint32_t r;
    asm("{ .reg .u64 t; cvta.to.shared.u64 t, %1; cvt.u32.u64 %0, t; }" : "=r"(r) : "l"(p));
    return r;
}
__device__ __forceinline__ void cp16(uint32_t dst, const void* src) {
    asm volatile("cp.async.cg.shared.global [%0], [%1], 16;" :: "r"(dst), "l"(src));
}
#define CP_COMMIT() asm volatile("cp.async.commit_group;")
#define CP_WAIT(n)  asm volatile("cp.async.wait_group %0;" :: "n"(n))

__device__ __forceinline__ uint32_t f2tf32(float v) {
    uint32_t r; asm("cvt.rna.tf32.f32 %0, %1;" : "=r"(r) : "f"(v));
    return r;
}

// m16n8k8 tf32 HMMA (baseline PTX, works on compute_103)
__device__ __forceinline__ void mma_tf32(float* d, const uint32_t* a, uint32_t b0, uint32_t b1) {
    asm volatile(
        "mma.sync.aligned.m16n8k8.row.col.f32.tf32.tf32.f32 "
        "{%0,%1,%2,%3}, {%4,%5,%6,%7}, {%8,%9}, {%0,%1,%2,%3};"
        : "+f"(d[0]), "+f"(d[1]), "+f"(d[2]), "+f"(d[3])
        : "r"(a[0]), "r"(a[1]), "r"(a[2]), "r"(a[3]), "r"(b0), "r"(b1));
}

// Hand-rolled grid barrier: all NCTA CTAs are co-resident (1 CTA/SM).
__device__ __forceinline__ void grid_sync() {
    __threadfence();
    __syncthreads();
    if (threadIdx.x == 0) {
        int g = g_gen;
        if (atomicAdd(&g_cnt, 1) == NCTA - 1) {
            g_cnt = 0;
            __threadfence();
            g_gen = g + 1;
        } else {
            while (g_gen == g) { }
        }
    }
    __syncthreads();
    __threadfence();
}

// ---------------------------------------------------------------------------
// Prep 1: W_x -> masked tf32, transposed to [k][gh]
// ---------------------------------------------------------------------------
__global__ void prep_wxp_kernel(const float* __restrict__ Wx, const float* __restrict__ mx) {
    const int i   = blockIdx.x * 256 + threadIdx.x;  // i = k*4096 + col
    const int col = i & 4095;
    const int k   = i >> 12;
    const size_t src = ((size_t)col << 10) + k;
    g_Wxp[i] = f2tf32(Wx[src] * mx[src]);
}

// ---------------------------------------------------------------------------
// Prep 2: W_h -> masked tf32, transposed to [k][col'], col' = nb*32 + g*8 + j,
// where h = nb*8 + j.
// ---------------------------------------------------------------------------
__global__ void prep_wp_kernel(const float* __restrict__ Wh, const float* __restrict__ mh) {
    const int i   = blockIdx.x * 256 + threadIdx.x;
    const int col = i & 4095;
    const int k   = i >> 12;
    const int g   = (col >> 3) & 3;
    const int h   = ((col >> 5) << 3) + (col & 7);
    const size_t src = ((size_t)g << 20) + ((size_t)h << 10) + k;
    g_Wp[i] = f2tf32(Wh[src] * mh[src]);
}

// ---------------------------------------------------------------------------
// Prep 3: H0 -> tf32 image (buffer 0); init grid-barrier state
// ---------------------------------------------------------------------------
__global__ void prep_h0_kernel(const float* __restrict__ H0) {
    const int i = blockIdx.x * 256 + threadIdx.x;   // < 65536
    g_Ht[0][i] = f2tf32(H0[i]);
    if (i == 0) { g_cnt = 0; g_gen = 0; }
}

// ---------------------------------------------------------------------------
// Phase 1: g_XW = inputs @ Wxp  via tf32 mma.sync (unchanged, 816us measured)
// ---------------------------------------------------------------------------
#define XW_SMEM_BYTES ((9216 + 8448) * 4)
__global__ __launch_bounds__(256) void gemm_xw_mma(const float* __restrict__ A) {
    extern __shared__ __align__(16) float dsm[];
    const int tid  = threadIdx.x;
    const int w    = tid >> 5;
    const int lane = tid & 31;
    const int tq   = lane >> 2;
    const int tr   = lane & 3;
    const int bm   = blockIdx.y * 128;
    const int bn   = blockIdx.x * 128;
    const int wm   = (w >> 2) * 64;
    const int wn   = (w & 3) * 32;

    const uint32_t sA = smem_u32(dsm);
    const uint32_t sB = sA + 9216u * 4u;

    #define XW_LOAD(kc_, st_)                                                 \
    {                                                                         \
        _Pragma("unroll")                                                     \
        for (int j_ = 0; j_ < 4; ++j_) {                                      \
            int e_ = tid + 256 * j_;                                          \
            int m_ = e_ >> 3, c_ = e_ & 7;                                    \
            cp16(sA + (st_) * 18432u + m_ * 144u + c_ * 16u,                  \
                 A + (size_t)(bm + m_) * 1024 + (kc_) * 32 + c_ * 4);         \
        }                                                                     \
        _Pragma("unroll")                                                     \
        for (int j_ = 0; j_ < 4; ++j_) {                                      \
            int e_ = tid + 256 * j_;                                          \
            int k_ = e_ >> 5, c_ = e_ & 31;                                   \
            cp16(sB + (st_) * 16896u + k_ * 528u + c_ * 16u,                  \
                 g_Wxp + ((size_t)((kc_) * 32 + k_) << 12) + bn + c_ * 4);    \
        }                                                                     \
        CP_COMMIT();                                                          \
    }

    float acc[4][4][4] = {};

    XW_LOAD(0, 0);

    for (int kc = 0; kc < 32; ++kc) {
        const int st = kc & 1;
        if (kc + 1 < 32) { XW_LOAD(kc + 1, st ^ 1); CP_WAIT(1); }
        else             { CP_WAIT(0); }
        __syncthreads();

        const float* Ab = dsm + st * 4608;           // [128][36]
        const float* Bb = dsm + 9216 + st * 4224;    // [32][132]
        #pragma unroll
        for (int ks = 0; ks < 4; ++ks) {
            const int k0 = ks * 8;
            uint32_t a[4][4];
            #pragma unroll
            for (int mi = 0; mi < 4; ++mi) {
                const int rm = wm + mi * 16;
                a[mi][0] = __float_as_uint(Ab[(rm + tq    ) * 36 + k0 + tr    ]);
                a[mi][1] = __float_as_uint(Ab[(rm + tq + 8) * 36 + k0 + tr    ]);
                a[mi][2] = __float_as_uint(Ab[(rm + tq    ) * 36 + k0 + tr + 4]);
                a[mi][3] = __float_as_uint(Ab[(rm + tq + 8) * 36 + k0 + tr + 4]);
            }
            #pragma unroll
            for (int ni = 0; ni < 4; ++ni) {
                uint32_t b0 = __float_as_uint(Bb[(k0 + tr    ) * 132 + wn + ni * 8 + tq]);
                uint32_t b1 = __float_as_uint(Bb[(k0 + tr + 4) * 132 + wn + ni * 8 + tq]);
                #pragma unroll
                for (int mi = 0; mi < 4; ++mi)
                    mma_tf32(acc[mi][ni], a[mi], b0, b1);
            }
        }
        __syncthreads();
    }
    #undef XW_LOAD

    #pragma unroll
    for (int mi = 0; mi < 4; ++mi) {
        const int r0 = bm + wm + mi * 16 + tq;
        #pragma unroll
        for (int ni = 0; ni < 4; ++ni) {
            const int cn = bn + wn + ni * 8 + 2 * tr;
            *(float2*)(g_XW + (size_t)r0 * GDIM + cn) =
                make_float2(acc[mi][ni][0], acc[mi][ni][1]);
            *(float2*)(g_XW + (size_t)(r0 + 8) * GDIM + cn) =
                make_float2(acc[mi][ni][2], acc[mi][ni][3]);
        }
    }
}

// ---------------------------------------------------------------------------
// Phase 2: PERSISTENT recurrence kernel — all 256 steps in one launch.
//  128 CTAs x 256 thr, 1 CTA/SM. CTA nb owns cols col'=nb*32+g*8+j
//  (h = nb*8+j, all 4 gates), all 64 batches.
//  Wh slice [1024 k][32 cols] preloaded to SMEM once (pad 36): reused 256x.
//  Per step: H (tf32 image, ping-pong in gmem) streamed via 3-stage cp.async;
//  split-K across warp halves; smem reduce; register-resident C; epilogue
//  writes fp32 out + tf32 H image; grid barrier.
//  smem floats: As[3][64][68] @0 (13056) ; Bs[1024][36] @13056 (36864)
// ---------------------------------------------------------------------------
#define PERS_SMEM_BYTES ((13056 + 36864) * 4)
__global__ __launch_bounds__(256) void lstm_persist(const float* __restrict__ bias,
                                                    const float* __restrict__ C0,
                                                    float* __restrict__ out) {
    extern __shared__ __align__(16) float dsm[];
    const int tid  = threadIdx.x;
    const int w    = tid >> 5;
    const int lane = tid & 31;
    const int tq   = lane >> 2;
    const int tr   = lane & 3;
    const int nb   = blockIdx.x;
    const int wb   = w & 3;
    const int kh   = w >> 2;

    const uint32_t sA = smem_u32(dsm);
    const uint32_t sB = sA + 13056u * 4u;

    // ---- one-time: preload Wh slice [1024][32] -> Bs[1024][36] ----
    {
        const uint32_t* Wp = g_Wp + nb * 32;
        #pragma unroll
        for (int j = 0; j < 32; ++j) {
            int e = tid + 256 * j;          // < 8192
            int k = e >> 3, c = e & 7;
            cp16(sB + k * 144u + c * 16u, Wp + ((size_t)k << 12) + c * 4);
        }
        CP_COMMIT();
        CP_WAIT(0);
        __syncthreads();
    }

    // ---- per-thread constants (epilogue threads: kh == 0) ----
    // c=0: (b0, h0) c=1: (b0, h1) c=2: (b1, h0) c=3: (b1, h1)
    const int b0r = 16 * wb + tq;
    const int h0r = nb * 8 + 2 * tr;
    float Creg[4];
    float bz[4][2];   // bias[gate][h0/h1]
    if (kh == 0) {
        Creg[0] = C0[(b0r << 10) + h0r];
        Creg[1] = C0[(b0r << 10) + h0r + 1];
        Creg[2] = C0[((b0r + 8) << 10) + h0r];
        Creg[3] = C0[((b0r + 8) << 10) + h0r + 1];
        #pragma unroll
        for (int g = 0; g < 4; ++g) {
            bz[g][0] = bias[g * 1024 + h0r];
            bz[g][1] = bias[g * 1024 + h0r + 1];
        }
    }

    const float* Bb = dsm + 13056;   // [1024][36]

    for (int t = 0; t < T_STEPS; ++t) {
        const uint32_t* Ht = g_Ht[t & 1];
        uint32_t* Hw = g_Ht[(t + 1) & 1];

        #define ST_LOADA(kc_, st_)                                            \
        {                                                                     \
            _Pragma("unroll")                                                 \
            for (int j_ = 0; j_ < 4; ++j_) {                                  \
                int e_ = tid + 256 * j_;                                      \
                int m_ = e_ >> 4, c_ = e_ & 15;                               \
                cp16(sA + (st_) * 17408u + m_ * 272u + c_ * 16u,              \
                     Ht + m_ * 1024 + (kc_) * 64 + c_ * 4);                   \
            }                                                                 \
            CP_COMMIT();                                                      \
        }

        float acc[4][4] = {};   // [gate][c]

        ST_LOADA(0, 0);
        ST_LOADA(1, 1);

        for (int kc = 0; kc < 16; ++kc) {
            const int st = kc % 3;
            if (kc + 2 < 16) { ST_LOADA(kc + 2, (kc + 2) % 3); CP_WAIT(2); }
            else             { CP_WAIT(0); }
            __syncthreads();

            const float* Ab = dsm + st * 4352;   // [64][68]
            #pragma unroll
            for (int ks = 0; ks < 4; ++ks) {
                const int k0 = kh * 32 + ks * 8;       // k within chunk
                const int kf = kc * 64 + k0;           // global k (for B)
                uint32_t a[4];
                a[0] = __float_as_uint(Ab[(16 * wb + tq    ) * 68 + k0 + tr    ]);
                a[1] = __float_as_uint(Ab[(16 * wb + tq + 8) * 68 + k0 + tr    ]);
                a[2] = __float_as_uint(Ab[(16 * wb + tq    ) * 68 + k0 + tr + 4]);
                a[3] = __float_as_uint(Ab[(16 * wb + tq + 8) * 68 + k0 + tr + 4]);
                #pragma unroll
                for (int g = 0; g < 4; ++g) {
                    uint32_t b0 = __float_as_uint(Bb[(kf + tr    ) * 36 + g * 8 + tq]);
                    uint32_t b1 = __float_as_uint(Bb[(kf + tr + 4) * 36 + g * 8 + tq]);
                    mma_tf32(acc[g], a, b0, b1);
                }
            }
            __syncthreads();
        }
        #undef ST_LOADA

        // K-half reduction via smem (A region, mainloop done)
        const int ridx = ((wb * 32 + lane) << 4);
        if (kh == 1) {
            #pragma unroll
            for (int g = 0; g < 4; ++g)
                #pragma unroll
                for (int c = 0; c < 4; ++c)
                    dsm[ridx + g * 4 + c] = acc[g][c];
        }
        __syncthreads();

        if (kh == 0) {
            #pragma unroll
            for (int g = 0; g < 4; ++g)
                #pragma unroll
                for (int c = 0; c < 4; ++c)
                    acc[g][c] += dsm[ridx + g * 4 + c];

            const float* xw = g_XW + ((size_t)t << 18);
            float* Ho = out + ((size_t)t << 16);

            #pragma unroll
            for (int c = 0; c < 4; ++c) {
                const int b = b0r + ((c >> 1) << 3);
                const int h = h0r + (c & 1);
                const float* xr = xw + ((size_t)b << 12);
                float pi = acc[0][c] + xr[h]        + bz[0][c & 1];
                float pf = acc[1][c] + xr[1024 + h] + bz[1][c & 1];
                float po = acc[2][c] + xr[2048 + h] + bz[2][c & 1];
                float pc = acc[3][c] + xr[3072 + h] + bz[3][c & 1];
                float Ig = 1.0f / (1.0f + __expf(-pi));
                float Fg = 1.0f / (1.0f + __expf(-pf));
                float Og = 1.0f / (1.0f + __expf(-po));
                float Ct = tanhf(pc);
                float cn = Fg * Creg[c] + Ig * Ct;
                Creg[c] = cn;
                float Hn = Og * tanhf(cn);
                Ho[(b << 10) + h] = Hn;
                Hw[(b << 10) + h] = f2tf32(Hn);
            }
        }

        grid_sync();
    }
}

// ---------------------------------------------------------------------------
// Launch
// ---------------------------------------------------------------------------
extern "C" void kernel_launch(void* const* d_in, const int* in_sizes, int n_in,
                              void* d_out, int out_size) {
    (void)in_sizes; (void)n_in; (void)out_size;
    const float* inputs = (const float*)d_in[0];
    const float* W_x    = (const float*)d_in[1];
    const float* W_h    = (const float*)d_in[2];
    const float* bias   = (const float*)d_in[3];
    const float* mask_x = (const float*)d_in[4];
    const float* mask_h = (const float*)d_in[5];
    const float* H0     = (const float*)d_in[6];
    const float* C0     = (const float*)d_in[7];
    float* out = (float*)d_out;

    cudaFuncSetAttribute(gemm_xw_mma,
                         cudaFuncAttributeMaxDynamicSharedMemorySize, XW_SMEM_BYTES);
    cudaFuncSetAttribute(lstm_persist,
                         cudaFuncAttributeMaxDynamicSharedMemorySize, PERS_SMEM_BYTES);

    prep_wxp_kernel<<<16384, 256>>>(W_x, mask_x);
    prep_wp_kernel <<<16384, 256>>>(W_h, mask_h);
    prep_h0_kernel <<<256, 256>>>(H0);

    gemm_xw_mma<<<dim3(GDIM / 128, TBROWS / 128), 256, XW_SMEM_BYTES>>>(inputs);

    lstm_persist<<<NCTA, 256, PERS_SMEM_BYTES>>>(bias, C0, out);
}

// round 9
// speedup vs baseline: 5.9233x; 1.5542x over previous
#include <cuda_runtime.h>
#include <cstdint>
#include <math.h>

// Problem constants
#define T_STEPS 256
#define BATCH   64
#define IDIM    1024
#define HDIM    1024
#define GDIM    4096
#define TBROWS  (T_STEPS * BATCH)
#define NCTA    128

// ---------------------------------------------------------------------------
// Device scratch
// ---------------------------------------------------------------------------
__device__ __align__(16) float    g_XW[(size_t)TBROWS * GDIM];    // X @ Wx^T fp32, [tb][g*1024+h]
__device__ __align__(16) uint32_t g_Wxp[(size_t)IDIM * GDIM];     // tf32 Wx^T, [k][gh]
__device__ __align__(16) uint32_t g_Wp[(size_t)GDIM * HDIM];      // tf32 Wh, fragment-interleaved
__device__ __align__(16) uint32_t g_Ht[2][(size_t)BATCH * HDIM];  // tf32 H, fragment-interleaved
__device__ int          g_cnt;
__device__ volatile int g_gen;

// ---------------------------------------------------------------------------
// Helpers
// ---------------------------------------------------------------------------
__device__ __forceinline__ uint32_t smem_u32(const void* p) {
    uint32_t r;
    asm("{ .reg .u64 t; cvta.to.shared.u64 t, %1; cvt.u32.u64 %0, t; }" : "=r"(r) : "l"(p));
    return r;
}
__device__ __forceinline__ void cp16(uint32_t dst, const void* src) {
    asm volatile("cp.async.cg.shared.global [%0], [%1], 16;" :: "r"(dst), "l"(src));
}
#define CP_COMMIT() asm volatile("cp.async.commit_group;")
#define CP_WAIT(n)  asm volatile("cp.async.wait_group %0;" :: "n"(n))

__device__ __forceinline__ uint32_t f2tf32(float v) {
    uint32_t r; asm("cvt.rna.tf32.f32 %0, %1;" : "=r"(r) : "f"(v));
    return r;
}

// m16n8k8 tf32 HMMA
__device__ __forceinline__ void mma_tf32(float* d, uint32_t a0, uint32_t a1,
                                         uint32_t a2, uint32_t a3,
                                         uint32_t b0, uint32_t b1) {
    asm volatile(
        "mma.sync.aligned.m16n8k8.row.col.f32.tf32.tf32.f32 "
        "{%0,%1,%2,%3}, {%4,%5,%6,%7}, {%8,%9}, {%0,%1,%2,%3};"
        : "+f"(d[0]), "+f"(d[1]), "+f"(d[2]), "+f"(d[3])
        : "r"(a0), "r"(a1), "r"(a2), "r"(a3), "r"(b0), "r"(b1));
}

__device__ __forceinline__ float fast_sig(float x) {
    return __fdividef(1.0f, 1.0f + __expf(-x));
}
__device__ __forceinline__ float fast_tanh(float x) {
    return 1.0f - __fdividef(2.0f, 1.0f + __expf(2.0f * x));
}

// Grid barrier: all NCTA CTAs co-resident (1 CTA/SM)
__device__ __forceinline__ void grid_sync() {
    __threadfence();
    __syncthreads();
    if (threadIdx.x == 0) {
        int g = g_gen;
        if (atomicAdd(&g_cnt, 1) == NCTA - 1) {
            g_cnt = 0;
            __threadfence();
            g_gen = g + 1;
        } else {
            while (g_gen == g) { __nanosleep(64); }
        }
    }
    __syncthreads();
    __threadfence();
}

// ---------------------------------------------------------------------------
// Prep 1: W_x -> masked tf32, transposed to [k][gh]
// ---------------------------------------------------------------------------
__global__ void prep_wxp_kernel(const float* __restrict__ Wx, const float* __restrict__ mx) {
    const int i   = blockIdx.x * 256 + threadIdx.x;
    const int col = i & 4095;
    const int k   = i >> 12;
    const size_t src = ((size_t)col << 10) + k;
    g_Wxp[i] = f2tf32(Wx[src] * mx[src]);
}

// ---------------------------------------------------------------------------
// Prep 2: W_h -> masked tf32, FRAGMENT-INTERLEAVED:
//  g_Wp[nb*32768 + ((kb*4 + g)*32 + lane)*2 + comp]
//    lane = 4*tq + tr ;  value = Whm[g][h = nb*8 + tq][k = kb*8 + tr + 4*comp]
// ---------------------------------------------------------------------------
__global__ void prep_wp_kernel(const float* __restrict__ Wh, const float* __restrict__ mh) {
    const int i    = blockIdx.x * 256 + threadIdx.x;   // < 4M
    const int comp = i & 1;
    const int lane = (i >> 1) & 31;
    const int g    = (i >> 6) & 3;
    const int kb   = (i >> 8) & 127;
    const int nb   = i >> 15;
    const int tq   = lane >> 2;
    const int tr   = lane & 3;
    const int h    = nb * 8 + tq;
    const int k    = kb * 8 + tr + 4 * comp;
    const size_t src = ((size_t)g << 20) + ((size_t)h << 10) + k;
    g_Wp[i] = f2tf32(Wh[src] * mh[src]);
}

// ---------------------------------------------------------------------------
// Prep 3: H0 -> fragment-interleaved tf32 image:
//  g_Ht[0][((kb*4 + mb)*32 + lane)*4 + comp]
//    comp = rowhalf + 2*khalf; m = mb*16 + rowhalf*8 + tq; h = kb*8 + khalf*4 + tr
// ---------------------------------------------------------------------------
__global__ void prep_h0_kernel(const float* __restrict__ H0) {
    const int i    = blockIdx.x * 256 + threadIdx.x;   // < 65536
    const int comp = i & 3;
    const int lane = (i >> 2) & 31;
    const int mb   = (i >> 7) & 3;
    const int kb   = i >> 9;
    const int tq   = lane >> 2;
    const int tr   = lane & 3;
    const int m    = mb * 16 + (comp & 1) * 8 + tq;
    const int h    = kb * 8 + (comp >> 1) * 4 + tr;
    g_Ht[0][i] = f2tf32(H0[m * 1024 + h]);
    if (i == 0) { g_cnt = 0; g_gen = 0; }
}

// ---------------------------------------------------------------------------
// Phase 1: g_XW = inputs @ Wxp  via tf32 mma.sync (measured 808us)
// ---------------------------------------------------------------------------
#define XW_SMEM_BYTES ((9216 + 8448) * 4)
__global__ __launch_bounds__(256) void gemm_xw_mma(const float* __restrict__ A) {
    extern __shared__ __align__(16) float dsm[];
    const int tid  = threadIdx.x;
    const int w    = tid >> 5;
    const int lane = tid & 31;
    const int tq   = lane >> 2;
    const int tr   = lane & 3;
    const int bm   = blockIdx.y * 128;
    const int bn   = blockIdx.x * 128;
    const int wm   = (w >> 2) * 64;
    const int wn   = (w & 3) * 32;

    const uint32_t sA = smem_u32(dsm);
    const uint32_t sB = sA + 9216u * 4u;

    #define XW_LOAD(kc_, st_)                                                 \
    {                                                                         \
        _Pragma("unroll")                                                     \
        for (int j_ = 0; j_ < 4; ++j_) {                                      \
            int e_ = tid + 256 * j_;                                          \
            int m_ = e_ >> 3, c_ = e_ & 7;                                    \
            cp16(sA + (st_) * 18432u + m_ * 144u + c_ * 16u,                  \
                 A + (size_t)(bm + m_) * 1024 + (kc_) * 32 + c_ * 4);         \
        }                                                                     \
        _Pragma("unroll")                                                     \
        for (int j_ = 0; j_ < 4; ++j_) {                                      \
            int e_ = tid + 256 * j_;                                          \
            int k_ = e_ >> 5, c_ = e_ & 31;                                   \
            cp16(sB + (st_) * 16896u + k_ * 528u + c_ * 16u,                  \
                 g_Wxp + ((size_t)((kc_) * 32 + k_) << 12) + bn + c_ * 4);    \
        }                                                                     \
        CP_COMMIT();                                                          \
    }

    float acc[4][4][4] = {};

    XW_LOAD(0, 0);

    for (int kc = 0; kc < 32; ++kc) {
        const int st = kc & 1;
        if (kc + 1 < 32) { XW_LOAD(kc + 1, st ^ 1); CP_WAIT(1); }
        else             { CP_WAIT(0); }
        __syncthreads();

        const float* Ab = dsm + st * 4608;           // [128][36]
        const float* Bb = dsm + 9216 + st * 4224;    // [32][132]
        #pragma unroll
        for (int ks = 0; ks < 4; ++ks) {
            const int k0 = ks * 8;
            uint32_t a[4][4];
            #pragma unroll
            for (int mi = 0; mi < 4; ++mi) {
                const int rm = wm + mi * 16;
                a[mi][0] = __float_as_uint(Ab[(rm + tq    ) * 36 + k0 + tr    ]);
                a[mi][1] = __float_as_uint(Ab[(rm + tq + 8) * 36 + k0 + tr    ]);
                a[mi][2] = __float_as_uint(Ab[(rm + tq    ) * 36 + k0 + tr + 4]);
                a[mi][3] = __float_as_uint(Ab[(rm + tq + 8) * 36 + k0 + tr + 4]);
            }
            #pragma unroll
            for (int ni = 0; ni < 4; ++ni) {
                uint32_t b0 = __float_as_uint(Bb[(k0 + tr    ) * 132 + wn + ni * 8 + tq]);
                uint32_t b1 = __float_as_uint(Bb[(k0 + tr + 4) * 132 + wn + ni * 8 + tq]);
                #pragma unroll
                for (int mi = 0; mi < 4; ++mi)
                    mma_tf32(acc[mi][ni], a[mi][0], a[mi][1], a[mi][2], a[mi][3], b0, b1);
            }
        }
        __syncthreads();
    }
    #undef XW_LOAD

    #pragma unroll
    for (int mi = 0; mi < 4; ++mi) {
        const int r0 = bm + wm + mi * 16 + tq;
        #pragma unroll
        for (int ni = 0; ni < 4; ++ni) {
            const int cn = bn + wn + ni * 8 + 2 * tr;
            *(float2*)(g_XW + (size_t)r0 * GDIM + cn) =
                make_float2(acc[mi][ni][0], acc[mi][ni][1]);
            *(float2*)(g_XW + (size_t)(r0 + 8) * GDIM + cn) =
                make_float2(acc[mi][ni][2], acc[mi][ni][3]);
        }
    }
}

// ---------------------------------------------------------------------------
// Phase 2: PERSISTENT recurrence, fragment-interleaved operands.
//  128 CTAs x 512 thr (16 warps), 1 CTA/SM. CTA nb owns 32 gate-cols
//  (h = nb*8+j, 4 gates). Warp w: kh = w>>2 (K quarter), wb = w&3 (batch 16s).
//  Wh frag-packed in SMEM once (128 KB). H image streamed per step via
//  linear cp.async (3-stage ring). Mainloop: 1 LDS.128 (A) + 4 LDS.64 (B)
//  + 4 MMA per k-block. 4-way split-K smem reduce. XW prefetched into regs.
//  smem floats: A ring 3*4096 @0 ; Wh 32768 @12288  => 180224 B
// ---------------------------------------------------------------------------
#define PERS_SMEM_BYTES ((3 * 4096 + 32768) * 4)
__global__ __launch_bounds__(512) void lstm_persist(const float* __restrict__ bias,
                                                    const float* __restrict__ C0,
                                                    float* __restrict__ out) {
    extern __shared__ __align__(16) float dsm[];
    const int tid  = threadIdx.x;
    const int w    = tid >> 5;
    const int lane = tid & 31;
    const int tq   = lane >> 2;
    const int tr   = lane & 3;
    const int nb   = blockIdx.x;
    const int wb   = w & 3;
    const int kh   = w >> 2;

    const uint32_t sA = smem_u32(dsm);
    const uint32_t sB = sA + 12288u * 4u;

    // ---- one-time: preload fragment-packed Wh slice (32768 u32) ----
    {
        const uint32_t* Wp = g_Wp + ((size_t)nb << 15);
        #pragma unroll
        for (int j = 0; j < 16; ++j) {
            int e = tid + 512 * j;          // float4 index < 8192
            cp16(sB + e * 16u, Wp + e * 4);
        }
        CP_COMMIT();
        CP_WAIT(0);
        __syncthreads();
    }

    // ---- per-thread constants ----
    const int b0r = 16 * wb + tq;
    const int h0r = nb * 8 + 2 * tr;
    float Creg[4];
    float bz[4][2];
    // interleaved H-image write base for this thread's 4 elements
    const int lane0 = 4 * tq + ((2 * tr) & 3);
    const int khf   = tr >> 1;
    const uint32_t hwbase = (uint32_t)(((nb * 4 + wb) * 32 + lane0) * 4 + 2 * khf);
    if (kh == 0) {
        Creg[0] = C0[(b0r << 10) + h0r];
        Creg[1] = C0[(b0r << 10) + h0r + 1];
        Creg[2] = C0[((b0r + 8) << 10) + h0r];
        Creg[3] = C0[((b0r + 8) << 10) + h0r + 1];
        #pragma unroll
        for (int g = 0; g < 4; ++g) {
            bz[g][0] = bias[g * 1024 + h0r];
            bz[g][1] = bias[g * 1024 + h0r + 1];
        }
    }

    for (int t = 0; t < T_STEPS; ++t) {
        const uint32_t* Ht = g_Ht[t & 1];
        uint32_t* Hw = g_Ht[(t + 1) & 1];

        // XW prefetch (registers; overlaps mainloop)
        float2 xp[4][2];
        if (kh == 0) {
            const float* x0 = g_XW + ((size_t)t << 18) + ((size_t)b0r << 12);
            const float* x1 = x0 + (8 << 12);
            #pragma unroll
            for (int g = 0; g < 4; ++g) {
                xp[g][0] = *(const float2*)(x0 + g * 1024 + h0r);
                xp[g][1] = *(const float2*)(x1 + g * 1024 + h0r);
            }
        }

        #define ST_LOADA(kc_, st_)                                            \
        {                                                                     \
            _Pragma("unroll")                                                 \
            for (int j_ = 0; j_ < 2; ++j_) {                                  \
                int e_ = tid + 512 * j_;                                      \
                cp16(sA + (st_) * 16384u + e_ * 16u,                          \
                     Ht + (kc_) * 4096 + e_ * 4);                             \
            }                                                                 \
            CP_COMMIT();                                                      \
        }

        float acc[4][4] = {};   // [gate][c]

        ST_LOADA(0, 0);
        ST_LOADA(1, 1);

        for (int kc = 0; kc < 16; ++kc) {
            const int st = kc % 3;
            if (kc + 2 < 16) { ST_LOADA(kc + 2, (kc + 2) % 3); CP_WAIT(2); }
            else             { CP_WAIT(0); }
            __syncthreads();

            #pragma unroll
            for (int ks = 0; ks < 2; ++ks) {
                const int kbl = kh * 2 + ks;        // local k-block (0..7)
                const int kbg = kc * 8 + kbl;       // global k-block
                uint4 a = ((const uint4*)dsm)[st * 1024 + (kbl * 4 + wb) * 32 + lane];
                #pragma unroll
                for (int g = 0; g < 4; ++g) {
                    uint2 b = ((const uint2*)(dsm + 12288))[(kbg * 4 + g) * 32 + lane];
                    mma_tf32(acc[g], a.x, a.y, a.z, a.w, b.x, b.y);
                }
            }
            __syncthreads();
        }
        #undef ST_LOADA

        // 4-way split-K reduce via smem (A ring region; mainloop done)
        if (kh) {
            float* rp = dsm + (kh - 1) * 2048 + wb * 32 + lane;
            #pragma unroll
            for (int g = 0; g < 4; ++g)
                #pragma unroll
                for (int c = 0; c < 4; ++c)
                    rp[(g * 4 + c) * 128] = acc[g][c];
        }
        __syncthreads();

        if (kh == 0) {
            const float* rp = dsm + wb * 32 + lane;
            #pragma unroll
            for (int g = 0; g < 4; ++g)
                #pragma unroll
                for (int c = 0; c < 4; ++c) {
                    const int o = (g * 4 + c) * 128;
                    acc[g][c] += rp[o] + rp[2048 + o] + rp[4096 + o];
                }

            float* Ho = out + ((size_t)t << 16);
            #pragma unroll
            for (int r = 0; r < 2; ++r) {
                const int c0 = 2 * r, c1 = 2 * r + 1;
                const int b  = b0r + 8 * r;
                float pi0 = acc[0][c0] + xp[0][r].x + bz[0][0];
                float pi1 = acc[0][c1] + xp[0][r].y + bz[0][1];
                float pf0 = acc[1][c0] + xp[1][r].x + bz[1][0];
                float pf1 = acc[1][c1] + xp[1][r].y + bz[1][1];
                float po0 = acc[2][c0] + xp[2][r].x + bz[2][0];
                float po1 = acc[2][c1] + xp[2][r].y + bz[2][1];
                float pc0 = acc[3][c0] + xp[3][r].x + bz[3][0];
                float pc1 = acc[3][c1] + xp[3][r].y + bz[3][1];
                float cn0 = fast_sig(pf0) * Creg[c0] + fast_sig(pi0) * fast_tanh(pc0);
                float cn1 = fast_sig(pf1) * Creg[c1] + fast_sig(pi1) * fast_tanh(pc1);
                Creg[c0] = cn0; Creg[c1] = cn1;
                float Hn0 = fast_sig(po0) * fast_tanh(cn0);
                float Hn1 = fast_sig(po1) * fast_tanh(cn1);
                *(float2*)(Ho + (b << 10) + h0r) = make_float2(Hn0, Hn1);
                Hw[hwbase + r]     = f2tf32(Hn0);
                Hw[hwbase + 4 + r] = f2tf32(Hn1);
            }
        }

        grid_sync();
    }
}

// ---------------------------------------------------------------------------
// Launch
// ---------------------------------------------------------------------------
extern "C" void kernel_launch(void* const* d_in, const int* in_sizes, int n_in,
                              void* d_out, int out_size) {
    (void)in_sizes; (void)n_in; (void)out_size;
    const float* inputs = (const float*)d_in[0];
    const float* W_x    = (const float*)d_in[1];
    const float* W_h    = (const float*)d_in[2];
    const float* bias   = (const float*)d_in[3];
    const float* mask_x = (const float*)d_in[4];
    const float* mask_h = (const float*)d_in[5];
    const float* H0     = (const float*)d_in[6];
    const float* C0     = (const float*)d_in[7];
    float* out = (float*)d_out;

    cudaFuncSetAttribute(gemm_xw_mma,
                         cudaFuncAttributeMaxDynamicSharedMemorySize, XW_SMEM_BYTES);
    cudaFuncSetAttribute(lstm_persist,
                         cudaFuncAttributeMaxDynamicSharedMemorySize, PERS_SMEM_BYTES);

    prep_wxp_kernel<<<16384, 256>>>(W_x, mask_x);
    prep_wp_kernel <<<16384, 256>>>(W_h, mask_h);
    prep_h0_kernel <<<256, 256>>>(H0);

    gemm_xw_mma<<<dim3(GDIM / 128, TBROWS / 128), 256, XW_SMEM_BYTES>>>(inputs);

    lstm_persist<<<NCTA, 512, PERS_SMEM_BYTES>>>(bias, C0, out);
}

// round 12
// speedup vs baseline: 6.4958x; 1.0967x over previous
#include <cuda_runtime.h>
#include <cstdint>
#include <math.h>

// Problem constants
#define T_STEPS 256
#define BATCH   64
#define IDIM    1024
#define HDIM    1024
#define GDIM    4096
#define TBROWS  (T_STEPS * BATCH)
#define NCTA    128

// ---------------------------------------------------------------------------
// Device scratch
// ---------------------------------------------------------------------------
__device__ __align__(16) float    g_XW[(size_t)TBROWS * GDIM];    // X @ Wx^T fp32, [tb][g*1024+h]
__device__ __align__(16) uint32_t g_Ai[(size_t)TBROWS * IDIM];    // tf32 inputs, A-fragment-packed
__device__ __align__(16) uint32_t g_Wxb[(size_t)IDIM * GDIM];     // tf32 Wx, B-fragment-packed
__device__ __align__(16) uint32_t g_Wp[(size_t)GDIM * HDIM];      // tf32 Wh, B-fragment-packed
__device__ __align__(16) uint32_t g_Ht[2][(size_t)BATCH * HDIM];  // tf32 H, A-fragment-packed
__device__ int          g_cnt;
__device__ volatile int g_gen;

// ---------------------------------------------------------------------------
// Helpers
// ---------------------------------------------------------------------------
__device__ __forceinline__ uint32_t smem_u32(const void* p) {
    uint32_t r;
    asm("{ .reg .u64 t; cvta.to.shared.u64 t, %1; cvt.u32.u64 %0, t; }" : "=r"(r) : "l"(p));
    return r;
}
__device__ __forceinline__ void cp16(uint32_t dst, const void* src) {
    asm volatile("cp.async.cg.shared.global [%0], [%1], 16;" :: "r"(dst), "l"(src));
}
#define CP_COMMIT() asm volatile("cp.async.commit_group;")
#define CP_WAIT(n)  asm volatile("cp.async.wait_group %0;" :: "n"(n))

__device__ __forceinline__ uint32_t f2tf32(float v) {
    uint32_t r; asm("cvt.rna.tf32.f32 %0, %1;" : "=r"(r) : "f"(v));
    return r;
}

// m16n8k8 tf32 HMMA
__device__ __forceinline__ void mma_tf32(float* d, uint32_t a0, uint32_t a1,
                                         uint32_t a2, uint32_t a3,
                                         uint32_t b0, uint32_t b1) {
    asm volatile(
        "mma.sync.aligned.m16n8k8.row.col.f32.tf32.tf32.f32 "
        "{%0,%1,%2,%3}, {%4,%5,%6,%7}, {%8,%9}, {%0,%1,%2,%3};"
        : "+f"(d[0]), "+f"(d[1]), "+f"(d[2]), "+f"(d[3])
        : "r"(a0), "r"(a1), "r"(a2), "r"(a3), "r"(b0), "r"(b1));
}

__device__ __forceinline__ float fast_sig(float x) {
    return __fdividef(1.0f, 1.0f + __expf(-x));
}
__device__ __forceinline__ float fast_tanh(float x) {
    return 1.0f - __fdividef(2.0f, 1.0f + __expf(2.0f * x));
}

// Grid barrier: all NCTA CTAs co-resident (1 CTA/SM)
__device__ __forceinline__ void grid_sync() {
    __threadfence();
    __syncthreads();
    if (threadIdx.x == 0) {
        int g = g_gen;
        if (atomicAdd(&g_cnt, 1) == NCTA - 1) {
            g_cnt = 0;
            __threadfence();
            g_gen = g + 1;
        } else {
            while (g_gen == g) { __nanosleep(32); }
        }
    }
    __syncthreads();
    __threadfence();
}

// ---------------------------------------------------------------------------
// Prep 1: inputs -> A-fragment-packed tf32 image.
//  g_Ai[((mb*128 + kb)*32 + lane)*4 + comp]; m = mb*16 + tq + 8*(comp&1),
//  k = kb*8 + tr + 4*(comp>>1).   (warp reads = 4 full 32B sectors)
// ---------------------------------------------------------------------------
__global__ void prep_ai_kernel(const float* __restrict__ X) {
    const int i    = blockIdx.x * 256 + threadIdx.x;    // < 16777216
    const int comp = i & 3;
    const int lane = (i >> 2) & 31;
    const int kb   = (i >> 7) & 127;
    const int mb   = i >> 14;
    const int tq   = lane >> 2, tr = lane & 3;
    const int m    = mb * 16 + tq + 8 * (comp & 1);
    const int k    = kb * 8 + tr + 4 * (comp >> 1);
    g_Ai[i] = f2tf32(X[(size_t)m * 1024 + k]);
}

// ---------------------------------------------------------------------------
// Prep 2: W_x -> masked tf32, B-fragment-packed.
//  g_Wxb[((nb8*128 + kb)*32 + lane)*2 + comp]; col = nb8*8 + tq (std gh),
//  k = kb*8 + tr + 4*comp.
// ---------------------------------------------------------------------------
__global__ void prep_wxb_kernel(const float* __restrict__ Wx, const float* __restrict__ mx) {
    const int i    = blockIdx.x * 256 + threadIdx.x;    // < 4194304
    const int comp = i & 1;
    const int lane = (i >> 1) & 31;
    const int kb   = (i >> 6) & 127;
    const int nb8  = i >> 13;
    const int tq   = lane >> 2, tr = lane & 3;
    const int col  = nb8 * 8 + tq;
    const int k    = kb * 8 + tr + 4 * comp;
    const size_t src = (size_t)col * 1024 + k;
    g_Wxb[i] = f2tf32(Wx[src] * mx[src]);
}

// ---------------------------------------------------------------------------
// Prep 3: W_h -> masked tf32, B-fragment-packed (per-CTA slices):
//  g_Wp[nb*32768 + ((kb*4 + g)*32 + lane)*2 + comp]; h = nb*8 + tq,
//  k = kb*8 + tr + 4*comp.
// ---------------------------------------------------------------------------
__global__ void prep_wp_kernel(const float* __restrict__ Wh, const float* __restrict__ mh) {
    const int i    = blockIdx.x * 256 + threadIdx.x;   // < 4M
    const int comp = i & 1;
    const int lane = (i >> 1) & 31;
    const int g    = (i >> 6) & 3;
    const int kb   = (i >> 8) & 127;
    const int nb   = i >> 15;
    const int tq   = lane >> 2, tr = lane & 3;
    const int h    = nb * 8 + tq;
    const int k    = kb * 8 + tr + 4 * comp;
    const size_t src = ((size_t)g << 20) + ((size_t)h << 10) + k;
    g_Wp[i] = f2tf32(Wh[src] * mh[src]);
}

// ---------------------------------------------------------------------------
// Prep 4: H0 -> A-fragment-packed tf32 image (buffer 0):
//  g_Ht[0][((kb*4 + mb)*32 + lane)*4 + comp]; m = mb*16 + (comp&1)*8 + tq,
//  h = kb*8 + (comp>>1)*4 + tr.
// ---------------------------------------------------------------------------
__global__ void prep_h0_kernel(const float* __restrict__ H0) {
    const int i    = blockIdx.x * 256 + threadIdx.x;   // < 65536
    const int comp = i & 3;
    const int lane = (i >> 2) & 31;
    const int mb   = (i >> 7) & 3;
    const int kb   = i >> 9;
    const int tq   = lane >> 2, tr = lane & 3;
    const int m    = mb * 16 + (comp & 1) * 8 + tq;
    const int h    = kb * 8 + (comp >> 1) * 4 + tr;
    g_Ht[0][i] = f2tf32(H0[m * 1024 + h]);
    if (i == 0) { g_cnt = 0; g_gen = 0; }
}

// ---------------------------------------------------------------------------
// Phase 1: g_XW = inputs @ Wx^T via tf32 mma, fragment-packed operands.
//  CTA 128m x 128n, 256 thr (8 warps: wm=w>>2 in {0,1} -> 64 rows;
//  wn=w&3 -> 32 cols). BK=32 (4 k-blocks), 3-stage ring, ONE sync/iter.
//  Per chunk/warp: 16 LDS.128 + 16 LDS.64 + 64 MMA.
//  smem u32: A ring 3*4096 @0 ; B ring 3*4096 @12288 => 98304 B
// ---------------------------------------------------------------------------
#define XW2_SMEM_BYTES (24576 * 4)
__global__ __launch_bounds__(256, 2) void gemm_xw2() {
    extern __shared__ __align__(16) uint32_t xsm[];
    const int tid  = threadIdx.x;
    const int w    = tid >> 5;
    const int lane = tid & 31;
    const int tq   = lane >> 2;
    const int tr   = lane & 3;
    const int wm   = w >> 2;            // 0..1
    const int wn   = w & 3;             // 0..3
    const int bm16 = blockIdx.y * 8;    // row-block16 base
    const int bn8  = blockIdx.x * 16;   // col-block8 base

    const uint32_t sA = smem_u32(xsm);
    const uint32_t sB = sA + 12288u * 4u;
    const uint4* A4 = (const uint4*)xsm;            // stage: st*1024 entries
    const uint2* B2 = (const uint2*)(xsm + 12288);  // stage: st*2048 entries

    #define XW_LOAD(kc_, st_)                                                 \
    {                                                                         \
        _Pragma("unroll")                                                     \
        for (int j_ = 0; j_ < 4; ++j_) {                                      \
            int e_ = tid + 256 * j_;                                          \
            int mbl_ = e_ >> 7, rest_ = e_ & 127;                             \
            cp16(sA + (st_) * 16384u + e_ * 16u,                              \
                 g_Ai + ((((size_t)(bm16 + mbl_) * 128 + (kc_) * 4) * 32)     \
                         + rest_) * 4);                                       \
        }                                                                     \
        _Pragma("unroll")                                                     \
        for (int j_ = 0; j_ < 4; ++j_) {                                      \
            int e_ = tid + 256 * j_;                                          \
            int nbl_ = e_ >> 6, rest_ = e_ & 63;                              \
            cp16(sB + (st_) * 16384u + e_ * 16u,                              \
                 g_Wxb + ((((size_t)(bn8 + nbl_) * 128 + (kc_) * 4) * 16)     \
                          + rest_) * 4);                                      \
        }                                                                     \
        CP_COMMIT();                                                          \
    }

    float acc[4][4][4] = {};

    XW_LOAD(0, 0);
    XW_LOAD(1, 1);

    for (int kc = 0; kc < 32; ++kc) {
        const int st = kc % 3;
        if (kc < 31) { CP_WAIT(1); } else { CP_WAIT(0); }
        __syncthreads();

        #pragma unroll
        for (int kbl = 0; kbl < 4; ++kbl) {
            uint4 a[4];
            #pragma unroll
            for (int mi = 0; mi < 4; ++mi)
                a[mi] = A4[st * 1024 + ((wm * 4 + mi) * 4 + kbl) * 32 + lane];
            #pragma unroll
            for (int ni = 0; ni < 4; ++ni) {
                uint2 b = B2[st * 2048 + ((wn * 4 + ni) * 4 + kbl) * 32 + lane];
                #pragma unroll
                for (int mi = 0; mi < 4; ++mi)
                    mma_tf32(acc[mi][ni], a[mi].x, a[mi].y, a[mi].z, a[mi].w,
                             b.x, b.y);
            }
        }
        if (kc + 2 < 32) XW_LOAD(kc + 2, (kc + 2) % 3);
    }
    #undef XW_LOAD

    const int bm = blockIdx.y * 128;
    const int bn = blockIdx.x * 128;
    #pragma unroll
    for (int mi = 0; mi < 4; ++mi) {
        const int r0 = bm + (wm * 4 + mi) * 16 + tq;
        #pragma unroll
        for (int ni = 0; ni < 4; ++ni) {
            const int cn = bn + (wn * 4 + ni) * 8 + 2 * tr;
            *(float2*)(g_XW + (size_t)r0 * GDIM + cn) =
                make_float2(acc[mi][ni][0], acc[mi][ni][1]);
            *(float2*)(g_XW + (size_t)(r0 + 8) * GDIM + cn) =
                make_float2(acc[mi][ni][2], acc[mi][ni][3]);
        }
    }
}

// ---------------------------------------------------------------------------
// Phase 2: PERSISTENT recurrence. 128 CTAs x 512 thr, 1 CTA/SM.
//  CTA nb owns 32 gate-cols (h = nb*8+j, 4 gates). Warp: kh=w>>2 (K quarter),
//  wb=w&3 (batch 16-group). Wh frag-packed in SMEM once (128 KB).
//  H streamed per step: 8 chunks x 32 KB, 3-stage ring, ONE sync per chunk.
//  4-way split-K smem reduce; register C; XW prefetched; fused epilogue.
//  smem u32: A ring 3*8192 @0 ; Wh 32768 @24576 => 229376 B
// ---------------------------------------------------------------------------
#define PERS_SMEM_BYTES ((3 * 8192 + 32768) * 4)
__global__ __launch_bounds__(512) void lstm_persist(const float* __restrict__ bias,
                                                    const float* __restrict__ C0,
                                                    float* __restrict__ out) {
    extern __shared__ __align__(16) uint32_t psm[];
    float* dsm = (float*)psm;
    const int tid  = threadIdx.x;
    const int w    = tid >> 5;
    const int lane = tid & 31;
    const int tq   = lane >> 2;
    const int tr   = lane & 3;
    const int nb   = blockIdx.x;
    const int wb   = w & 3;
    const int kh   = w >> 2;

    const uint32_t sA = smem_u32(psm);
    const uint32_t sB = sA + 24576u * 4u;
    const uint4* A4  = (const uint4*)psm;           // stage: st*2048 entries
    const uint2* Wh2 = (const uint2*)(psm + 24576);

    // ---- one-time: preload fragment-packed Wh slice (32768 u32) ----
    {
        const uint32_t* Wp = g_Wp + ((size_t)nb << 15);
        #pragma unroll
        for (int j = 0; j < 16; ++j) {
            int e = tid + 512 * j;          // float4 index < 8192
            cp16(sB + e * 16u, Wp + e * 4);
        }
        CP_COMMIT();
        CP_WAIT(0);
        __syncthreads();
    }

    // ---- per-thread constants ----
    const int b0r = 16 * wb + tq;
    const int h0r = nb * 8 + 2 * tr;
    float Creg[4];
    float bz[4][2];
    const int lane0 = 4 * tq + ((2 * tr) & 3);
    const int khf   = tr >> 1;
    const uint32_t hwbase = (uint32_t)(((nb * 4 + wb) * 32 + lane0) * 4 + 2 * khf);
    if (kh == 0) {
        Creg[0] = C0[(b0r << 10) + h0r];
        Creg[1] = C0[(b0r << 10) + h0r + 1];
        Creg[2] = C0[((b0r + 8) << 10) + h0r];
        Creg[3] = C0[((b0r + 8) << 10) + h0r + 1];
        #pragma unroll
        for (int g = 0; g < 4; ++g) {
            bz[g][0] = bias[g * 1024 + h0r];
            bz[g][1] = bias[g * 1024 + h0r + 1];
        }
    }

    for (int t = 0; t < T_STEPS; ++t) {
        const uint32_t* Ht = g_Ht[t & 1];
        uint32_t* Hw = g_Ht[(t + 1) & 1];

        // XW prefetch (registers; overlaps mainloop)
        float2 xp[4][2];
        if (kh == 0) {
            const float* x0 = g_XW + ((size_t)t << 18) + ((size_t)b0r << 12);
            const float* x1 = x0 + (8 << 12);
            #pragma unroll
            for (int g = 0; g < 4; ++g) {
                xp[g][0] = *(const float2*)(x0 + g * 1024 + h0r);
                xp[g][1] = *(const float2*)(x1 + g * 1024 + h0r);
            }
        }

        #define ST_LOADA(kc_, st_)                                            \
        {                                                                     \
            _Pragma("unroll")                                                 \
            for (int j_ = 0; j_ < 4; ++j_) {                                  \
                int e_ = tid + 512 * j_;                                      \
                cp16(sA + (st_) * 32768u + e_ * 16u,                          \
                     Ht + (kc_) * 8192 + e_ * 4);                             \
            }                                                                 \
            CP_COMMIT();                                                      \
        }

        float acc[4][4] = {};   // [gate][c]

        ST_LOADA(0, 0);
        ST_LOADA(1, 1);

        for (int kc = 0; kc < 8; ++kc) {
            const int st = kc % 3;
            if (kc < 7) { CP_WAIT(1); } else { CP_WAIT(0); }
            __syncthreads();

            #pragma unroll
            for (int ks = 0; ks < 4; ++ks) {
                const int kbl = kh * 4 + ks;        // k-block within chunk
                const int kbg = kc * 16 + kbl;      // global k-block
                uint4 a = A4[st * 2048 + (kbl * 4 + wb) * 32 + lane];
                #pragma unroll
                for (int g = 0; g < 4; ++g) {
                    uint2 b = Wh2[(kbg * 4 + g) * 32 + lane];
                    mma_tf32(acc[g], a.x, a.y, a.z, a.w, b.x, b.y);
                }
            }
            if (kc + 2 < 8) ST_LOADA(kc + 2, (kc + 2) % 3);
        }
        #undef ST_LOADA

        // 4-way split-K reduce via smem (stage-0 region; safe: stage 0 reads
        // ended before the top-of-iter-7 sync, writes happen after it)
        if (kh) {
            float* rp = dsm + (kh - 1) * 2048 + wb * 32 + lane;
            #pragma unroll
            for (int g = 0; g < 4; ++g)
                #pragma unroll
                for (int c = 0; c < 4; ++c)
                    rp[(g * 4 + c) * 128] = acc[g][c];
        }
        __syncthreads();

        if (kh == 0) {
            const float* rp = dsm + wb * 32 + lane;
            #pragma unroll
            for (int g = 0; g < 4; ++g)
                #pragma unroll
                for (int c = 0; c < 4; ++c) {
                    const int o = (g * 4 + c) * 128;
                    acc[g][c] += rp[o] + rp[2048 + o] + rp[4096 + o];
                }

            float* Ho = out + ((size_t)t << 16);
            #pragma unroll
            for (int r = 0; r < 2; ++r) {
                const int c0 = 2 * r, c1 = 2 * r + 1;
                const int b  = b0r + 8 * r;
                float pi0 = acc[0][c0] + xp[0][r].x + bz[0][0];
                float pi1 = acc[0][c1] + xp[0][r].y + bz[0][1];
                float pf0 = acc[1][c0] + xp[1][r].x + bz[1][0];
                float pf1 = acc[1][c1] + xp[1][r].y + bz[1][1];
                float po0 = acc[2][c0] + xp[2][r].x + bz[2][0];
                float po1 = acc[2][c1] + xp[2][r].y + bz[2][1];
                float pc0 = acc[3][c0] + xp[3][r].x + bz[3][0];
                float pc1 = acc[3][c1] + xp[3][r].y + bz[3][1];
                float cn0 = fast_sig(pf0) * Creg[c0] + fast_sig(pi0) * fast_tanh(pc0);
                float cn1 = fast_sig(pf1) * Creg[c1] + fast_sig(pi1) * fast_tanh(pc1);
                Creg[c0] = cn0; Creg[c1] = cn1;
                float Hn0 = fast_sig(po0) * fast_tanh(cn0);
                float Hn1 = fast_sig(po1) * fast_tanh(cn1);
                *(float2*)(Ho + (b << 10) + h0r) = make_float2(Hn0, Hn1);
                Hw[hwbase + r]     = f2tf32(Hn0);
                Hw[hwbase + 4 + r] = f2tf32(Hn1);
            }
        }

        grid_sync();
    }
}

// ---------------------------------------------------------------------------
// Launch
// ---------------------------------------------------------------------------
extern "C" void kernel_launch(void* const* d_in, const int* in_sizes, int n_in,
                              void* d_out, int out_size) {
    (void)in_sizes; (void)n_in; (void)out_size;
    const float* inputs = (const float*)d_in[0];
    const float* W_x    = (const float*)d_in[1];
    const float* W_h    = (const float*)d_in[2];
    const float* bias   = (const float*)d_in[3];
    const float* mask_x = (const float*)d_in[4];
    const float* mask_h = (const float*)d_in[5];
    const float* H0     = (const float*)d_in[6];
    const float* C0     = (const float*)d_in[7];
    float* out = (float*)d_out;

    cudaFuncSetAttribute(gemm_xw2,
                         cudaFuncAttributeMaxDynamicSharedMemorySize, XW2_SMEM_BYTES);
    cudaFuncSetAttribute(lstm_persist,
                         cudaFuncAttributeMaxDynamicSharedMemorySize, PERS_SMEM_BYTES);

    prep_ai_kernel <<<65536, 256>>>(inputs);
    prep_wxb_kernel<<<16384, 256>>>(W_x, mask_x);
    prep_wp_kernel <<<16384, 256>>>(W_h, mask_h);
    prep_h0_kernel <<<256, 256>>>(H0);

    gemm_xw2<<<dim3(GDIM / 128, TBROWS / 128), 256, XW2_SMEM_BYTES>>>();

    lstm_persist<<<NCTA, 512, PERS_SMEM_BYTES>>>(bias, C0, out);
}